// round 6
// baseline (speedup 1.0000x reference)
#include <cuda_runtime.h>
#include <math.h>
#include <stdint.h>

// Problem constants
#define Bb 32
#define Tt 64
#define Ee 64
#define Uu 32
#define D0 300
#define D1 100
#define Ss 9
#define CELL 64
#define Cc 6
#define ROWS (Bb*Tt)      // 2048
#define G4E (4*Ee)        // 256
#define KC 100            // uniform K-chunk

// Device scratch: mod0 xproj split into 3 K-chunk partials
__device__ float g_xp0a[ROWS * G4E];
__device__ float g_xp0b[ROWS * G4E];
__device__ float g_xp0c[ROWS * G4E];
__device__ float g_xp1 [ROWS * G4E];
__device__ float g_h0[ROWS * Ee];
__device__ float g_h1[ROWS * Ee];
__device__ float g_krT[Ee * Uu];   // [e][u]
__device__ float g_kiT[Ee * Uu];

typedef unsigned long long u64;

// ---------------------------------------------------------------------------
// fast activations: single-instruction MUFU.TANH
// ---------------------------------------------------------------------------
__device__ __forceinline__ float tanha(float x) {
    float y;
    asm("tanh.approx.f32 %0, %1;" : "=f"(y) : "f"(x));
    return y;
}
__device__ __forceinline__ float fsig(float x) {
    return fmaf(tanha(0.5f * x), 0.5f, 0.5f);
}

// packed f32x2 helpers (Blackwell)
__device__ __forceinline__ u64 ffma2(u64 a, u64 b, u64 c) {
    u64 d;
    asm("fma.rn.f32x2 %0, %1, %2, %3;" : "=l"(d) : "l"(a), "l"(b), "l"(c));
    return d;
}
__device__ __forceinline__ u64 fadd2(u64 a, u64 b) {
    u64 d;
    asm("add.rn.f32x2 %0, %1, %2;" : "=l"(d) : "l"(a), "l"(b));
    return d;
}
__device__ __forceinline__ void unpk2(float& lo, float& hi, u64 v) {
    asm("mov.b64 {%0,%1}, %2;" : "=f"(lo), "=f"(hi) : "l"(v));
}

// ---------------------------------------------------------------------------
// Kernel 1: input-projection GEMM, uniform K=100 chunks + prep slice.
// grid = (5, 32, 4): x in [0,4) -> 64-wide N tiles; x==4,y==0,z==0 -> prep.
// z = 0,1,2 -> mod0 K-chunk z; z = 3 -> mod1.
// Tiles: BM=64, BN=64, BK=16. 256 threads, 4m x 4n microtile via f32x2:
// A tile stored DUPLICATED ((a,a) pairs) so LDS yields packed operands;
// per kk: 3x LDS.128 + 8x FFMA2 for 16 MACs. Double-buffered, 1 barrier/tile.
// ---------------------------------------------------------------------------
#define BKK 16
__global__ void __launch_bounds__(256) gemm_xproj(
    const float* __restrict__ x0, const float* __restrict__ Wih0,
    const float* __restrict__ bih0, const float* __restrict__ bhh0,
    const float* __restrict__ x1, const float* __restrict__ Wih1,
    const float* __restrict__ bih1, const float* __restrict__ bhh1,
    const float* __restrict__ umask, const float* __restrict__ mk) {

    if (blockIdx.x == 4) {
        if (blockIdx.y != 0 || blockIdx.z != 0) return;
        __shared__ float inv_norm[Uu];
        int tid = threadIdx.x;
        if (tid < Uu) {
            float s = 0.f;
            const float* p = mk + tid * (Ee * 2);
            #pragma unroll 8
            for (int i = 0; i < Ee * 2; i++) s += p[i] * p[i];
            inv_norm[tid] = 1.f / fmaxf(sqrtf(s), 1e-12f);
        }
        __syncthreads();
        for (int idx = tid; idx < Uu * Ee; idx += blockDim.x) {
            int u = idx >> 6;
            int e = idx & 63;
            float inv = inv_norm[u];
            g_krT[e * Uu + u] = mk[(u * Ee + e) * 2 + 0] * inv;
            g_kiT[e * Uu + u] = mk[(u * Ee + e) * 2 + 1] * inv;
        }
        return;
    }

    int z = blockIdx.z;
    bool mod1 = (z == 3);
    const float* A   = mod1 ? x1 : x0;
    const float* W   = mod1 ? Wih1 : Wih0;
    const float* bih = mod1 ? bih1 : bih0;
    const float* bhh = mod1 ? bhh1 : bhh0;
    float* out = (z == 0) ? g_xp0a : (z == 1) ? g_xp0b : (z == 2) ? g_xp0c : g_xp1;
    const int Ks = mod1 ? D1 : D0;
    const int k0 = mod1 ? 0 : z * KC;
    const bool addb = (z == 0) || mod1;

    // A duplicated: Asd[k][2m+s] = a_m for s=0,1. Row stride 136 (544B, 16B mult).
    __shared__ __align__(16) float Asd[2][BKK][136];
    __shared__ __align__(16) float Ws [2][BKK][68];

    int tid = threadIdx.x;
    int lk = tid & 15;          // k within tile
    int lm = tid >> 4;          // 0..15
    int bm = blockIdx.y * 64, bn = blockIdx.x * 64;

    const float* Ab = A + (size_t)(bm + lm) * Ks + k0;
    const float* Wb = W + (size_t)(bn + lm) * Ks + k0;
    const size_t rs = (size_t)16 * Ks;

    const int ntiles = (KC + BKK - 1) / BKK;   // 7

    float av[4], wv[4];
    #pragma unroll
    for (int j = 0; j < 4; j++) {
        av[j] = Ab[j * rs + lk];
        wv[j] = Wb[j * rs + lk];
    }
    #pragma unroll
    for (int j = 0; j < 4; j++) {
        *(float2*)&Asd[0][lk][2 * (lm + 16 * j)] = make_float2(av[j], av[j]);
        Ws[0][lk][lm + 16 * j] = wv[j];
    }
    __syncthreads();

    u64 accp[4][2];
    #pragma unroll
    for (int i = 0; i < 4; i++) { accp[i][0] = 0ull; accp[i][1] = 0ull; }

    int tx = tid & 15;          // n-quad: cols tx*4..+3
    int ty = tid >> 4;          // m-quad: rows ty*4..+3

    for (int tl = 0; tl < ntiles; tl++) {
        int cur = tl & 1;
        bool has = (tl + 1) < ntiles;
        if (has) {
            int k = (tl + 1) * BKK + lk;
            bool v = k < KC;
            #pragma unroll
            for (int j = 0; j < 4; j++) {
                av[j] = v ? Ab[j * rs + k] : 0.f;
                wv[j] = v ? Wb[j * rs + k] : 0.f;
            }
        }
        #pragma unroll
        for (int kk = 0; kk < BKK; kk++) {
            ulonglong2 ad0 = *(const ulonglong2*)&Asd[cur][kk][ty * 8];
            ulonglong2 ad1 = *(const ulonglong2*)&Asd[cur][kk][ty * 8 + 4];
            union { float4 f; ulonglong2 u; } wu;
            wu.f = *(const float4*)&Ws[cur][kk][tx * 4];
            accp[0][0] = ffma2(ad0.x, wu.u.x, accp[0][0]);
            accp[0][1] = ffma2(ad0.x, wu.u.y, accp[0][1]);
            accp[1][0] = ffma2(ad0.y, wu.u.x, accp[1][0]);
            accp[1][1] = ffma2(ad0.y, wu.u.y, accp[1][1]);
            accp[2][0] = ffma2(ad1.x, wu.u.x, accp[2][0]);
            accp[2][1] = ffma2(ad1.x, wu.u.y, accp[2][1]);
            accp[3][0] = ffma2(ad1.y, wu.u.x, accp[3][0]);
            accp[3][1] = ffma2(ad1.y, wu.u.y, accp[3][1]);
        }
        if (has) {
            int nb = cur ^ 1;
            #pragma unroll
            for (int j = 0; j < 4; j++) {
                *(float2*)&Asd[nb][lk][2 * (lm + 16 * j)] = make_float2(av[j], av[j]);
                Ws[nb][lk][lm + 16 * j] = wv[j];
            }
        }
        __syncthreads();
    }

    int n = bn + tx * 4;
    float bv0 = 0.f, bv1 = 0.f, bv2 = 0.f, bv3 = 0.f;
    if (addb) {
        bv0 = bih[n + 0] + bhh[n + 0];
        bv1 = bih[n + 1] + bhh[n + 1];
        bv2 = bih[n + 2] + bhh[n + 2];
        bv3 = bih[n + 3] + bhh[n + 3];
    }
    #pragma unroll
    for (int i = 0; i < 4; i++) {
        int m = bm + ty * 4 + i;
        float um = umask[m];
        float c0, c1, c2, c3;
        unpk2(c0, c1, accp[i][0]);
        unpk2(c2, c3, accp[i][1]);
        float4 o;
        o.x = um * c0 + bv0;
        o.y = um * c1 + bv1;
        o.z = um * c2 + bv2;
        o.w = um * c3 + bv3;
        *(float4*)&out[(size_t)m * G4E + n] = o;
    }
}

// ---------------------------------------------------------------------------
// Kernel 2: LSTM recurrence (shuffle gather with direct xor-3, double-buffered
// h, one barrier per step, prefetched xp with 3-chunk sum for mod0, MUFU.TANH).
// ---------------------------------------------------------------------------
__global__ void __launch_bounds__(256, 1) lstm_kernel(
    const float* __restrict__ Whh0, const float* __restrict__ Whh1) {
    int mod = blockIdx.x >> 5;
    int b = blockIdx.x & 31;
    const float* Whh = mod ? Whh1 : Whh0;
    size_t off = (size_t)b * Tt * G4E;
    const float* xpa = (mod ? g_xp1 : g_xp0a) + off;
    const float* xpb = (mod ? g_xp1 : g_xp0b) + off;
    const float* xpc = (mod ? g_xp1 : g_xp0c) + off;
    float* hout = (mod ? g_h1 : g_h0) + (size_t)b * Tt * Ee;

    int tid = threadIdx.x;
    int w = tid >> 5, l = tid & 31;
    int gt = l & 3;
    int cell = w * 8 + (l >> 2);
    int r = gt * 64 + cell;

    u64 wp[32];
    {
        const float2* src = (const float2*)(Whh + (size_t)r * Ee);
        #pragma unroll
        for (int i = 0; i < 32; i++) {
            union { float2 f; u64 u; } cv;
            cv.f = src[i];
            wp[i] = cv.u;
        }
    }

    __shared__ __align__(16) float hs[2][Ee];
    if (tid < Ee) hs[0][tid] = 0.f;
    float c = 0.f;
    __syncthreads();

    float gpre;
    {
        float ga = xpa[r], gb = xpb[r], gc = xpc[r];
        gpre = mod ? ga : (ga + gb + gc);
    }
    #pragma unroll 1
    for (int t = 0; t < Tt; t++) {
        float gnext = 0.f;
        if (t + 1 < Tt) {
            int idx = (t + 1) * G4E + r;
            float ga = xpa[idx], gb = xpb[idx], gc = xpc[idx];
            gnext = mod ? ga : (ga + gb + gc);
        }

        const ulonglong2* h2 = (const ulonglong2*)hs[t & 1];
        u64 a0 = 0ull, a1 = 0ull, a2 = 0ull, a3 = 0ull;
        #pragma unroll
        for (int i = 0; i < 16; i += 2) {
            ulonglong2 hv = h2[i];
            a0 = ffma2(wp[2 * i + 0], hv.x, a0);
            a1 = ffma2(wp[2 * i + 1], hv.y, a1);
            ulonglong2 hv2 = h2[i + 1];
            a2 = ffma2(wp[2 * i + 2], hv2.x, a2);
            a3 = ffma2(wp[2 * i + 3], hv2.y, a3);
        }
        u64 s = fadd2(fadd2(a0, a1), fadd2(a2, a3));
        float lo, hi;
        unpk2(lo, hi, s);
        float g = gpre + lo + hi;
        gpre = gnext;

        float act = (gt == 2) ? tanha(g) : fsig(g);

        // independent gathers (depth-1 shuffle chain)
        float v1 = __shfl_xor_sync(0xffffffffu, act, 1);
        float v2 = __shfl_xor_sync(0xffffffffu, act, 2);
        float v3 = __shfl_xor_sync(0xffffffffu, act, 3);

        if (gt == 0) {
            // act=sig(i), v1=sig(f), v2=tanh(g), v3=sig(o)
            c = v1 * c + act * v2;
            float h = tanha(v3 * tanha(c));
            hs[(t + 1) & 1][cell] = h;
            hout[t * Ee + cell] = h;
        }
        __syncthreads();
    }
}

// ---------------------------------------------------------------------------
// Kernel 3: normalize + phase + measurement + MLP + log_softmax.
// 512 blocks x 256 threads, 4 rows/block. Weights read via __ldg (L1-resident
// across CTAs within the launch) — no smem staging.
// ---------------------------------------------------------------------------
__global__ void __launch_bounds__(256) epilogue_kernel(
    const float* __restrict__ smask, const float* __restrict__ phase_table,
    const float* __restrict__ W1, const float* __restrict__ b1,
    const float* __restrict__ W2, const float* __restrict__ b2,
    float* __restrict__ out) {
    __shared__ float r0s[4][Ee], i0s[4][Ee], r1s[4][Ee], i1s[4][Ee];
    __shared__ float ms[4][2 * Uu];
    __shared__ float hids[4][CELL];
    __shared__ float preds[4][8];
    __shared__ float part[4][2][2];
    __shared__ int sidx[4];
    __shared__ float lse_s[4];

    int tid = threadIdx.x;
    int slot = tid >> 6;
    int lt = tid & 63;
    int row = blockIdx.x * 4 + slot;

    float h0 = g_h0[row * Ee + lt];
    float h1 = g_h1[row * Ee + lt];
    float v0 = h0 * h0, v1 = h1 * h1;
    #pragma unroll
    for (int off = 16; off; off >>= 1) {
        v0 += __shfl_xor_sync(0xffffffffu, v0, off);
        v1 += __shfl_xor_sync(0xffffffffu, v1, off);
    }
    if ((tid & 31) == 0) { part[slot][lt >> 5][0] = v0; part[slot][lt >> 5][1] = v1; }
    if (lt == 0) {
        const float* sm = smask + row * Ss;
        float best = sm[0]; int bi = 0;
        #pragma unroll
        for (int e = 1; e < Ss; e++) { float v = sm[e]; if (v > best) { best = v; bi = e; } }
        sidx[slot] = bi;
    }
    __syncthreads();

    float s0 = part[slot][0][0] + part[slot][1][0];
    float s1 = part[slot][0][1] + part[slot][1][1];
    float inv0 = 1.f / fmaxf(sqrtf(s0), 1e-12f);
    float inv1 = 1.f / fmaxf(sqrtf(s1), 1e-12f);
    float n0 = h0 * inv0, n1 = h1 * inv1;

    float ph = __ldg(&phase_table[sidx[slot] * Ee + lt]);
    float cp = cosf(ph), sp = sinf(ph);
    r0s[slot][lt] = cp * n0; i0s[slot][lt] = sp * n0;
    r1s[slot][lt] = cp * n1; i1s[slot][lt] = sp * n1;
    __syncthreads();

    {
        int mo = lt >> 5;
        int uu = lt & 31;
        const float* R = mo ? r1s[slot] : r0s[slot];
        const float* I = mo ? i1s[slot] : i0s[slot];
        float pr = 0.f, pi = 0.f;
        #pragma unroll 16
        for (int e = 0; e < Ee; e++) {
            float kr = __ldg(&g_krT[e * Uu + uu]);
            float ki = __ldg(&g_kiT[e * Uu + uu]);
            float rr = R[e], im = I[e];
            pr += kr * rr - ki * im;
            pi += ki * rr + kr * im;
        }
        ms[slot][lt] = pr * pr + pi * pi;
    }
    __syncthreads();

    {
        int cc = lt;
        float acc = __ldg(&b1[cc]);
        const float* w1r = W1 + cc * CELL;
        #pragma unroll 16
        for (int k = 0; k < CELL; k++) acc += ms[slot][k] * __ldg(&w1r[k]);
        hids[slot][cc] = fmaxf(acc, 0.f);
    }
    __syncthreads();

    if (lt < Cc) {
        float acc = __ldg(&b2[lt]);
        const float* w2 = W2 + lt * CELL;
        #pragma unroll 16
        for (int k = 0; k < CELL; k++) acc += hids[slot][k] * __ldg(&w2[k]);
        preds[slot][lt] = tanhf(acc);
    }
    __syncthreads();

    if (lt == 0) {
        float m = preds[slot][0];
        #pragma unroll
        for (int k = 1; k < Cc; k++) m = fmaxf(m, preds[slot][k]);
        float se = 0.f;
        #pragma unroll
        for (int k = 0; k < Cc; k++) se += expf(preds[slot][k] - m);
        lse_s[slot] = m + logf(se);
    }
    __syncthreads();

    if (lt < Cc) out[row * Cc + lt] = preds[slot][lt] - lse_s[slot];
}

// ---------------------------------------------------------------------------
extern "C" void kernel_launch(void* const* d_in, const int* in_sizes, int n_in,
                              void* d_out, int out_size) {
    const float* x0        = (const float*)d_in[0];
    const float* x1        = (const float*)d_in[1];
    const float* smask     = (const float*)d_in[2];
    const float* umask     = (const float*)d_in[3];
    const float* W_ih0     = (const float*)d_in[4];
    const float* W_hh0     = (const float*)d_in[5];
    const float* b_ih0     = (const float*)d_in[6];
    const float* b_hh0     = (const float*)d_in[7];
    const float* W_ih1     = (const float*)d_in[8];
    const float* W_hh1     = (const float*)d_in[9];
    const float* b_ih1     = (const float*)d_in[10];
    const float* b_hh1     = (const float*)d_in[11];
    const float* phase_tab = (const float*)d_in[12];
    const float* meas_k    = (const float*)d_in[13];
    const float* W1        = (const float*)d_in[14];
    const float* b1        = (const float*)d_in[15];
    const float* W2        = (const float*)d_in[16];
    const float* b2        = (const float*)d_in[17];
    float* out = (float*)d_out;

    dim3 ggrid(5, ROWS / 64, 4);   // (5, 32, 4): 3 mod0 chunks + mod1, uniform K=100
    gemm_xproj<<<ggrid, 256>>>(x0, W_ih0, b_ih0, b_hh0,
                               x1, W_ih1, b_ih1, b_hh1, umask, meas_k);

    lstm_kernel<<<64, 256>>>(W_hh0, W_hh1);

    epilogue_kernel<<<ROWS / 4, 256>>>(smask, phase_tab, W1, b1, W2, b2, out);
}

// round 7
// speedup vs baseline: 1.3306x; 1.3306x over previous
#include <cuda_runtime.h>
#include <math.h>
#include <stdint.h>

// Problem constants
#define Bb 32
#define Tt 64
#define Ee 64
#define Uu 32
#define D0 300
#define D1 100
#define Ss 9
#define CELL 64
#define Cc 6
#define ROWS (Bb*Tt)      // 2048
#define G4E (4*Ee)        // 256
#define KC 100            // uniform K-chunk

// Device scratch: mod0 xproj split into 3 K-chunk partials
__device__ float g_xp0a[ROWS * G4E];
__device__ float g_xp0b[ROWS * G4E];
__device__ float g_xp0c[ROWS * G4E];
__device__ float g_xp1 [ROWS * G4E];
__device__ float g_h0[ROWS * Ee];
__device__ float g_h1[ROWS * Ee];
__device__ float g_krT[Ee * Uu];   // [e][u]
__device__ float g_kiT[Ee * Uu];

typedef unsigned long long u64;

// ---------------------------------------------------------------------------
// fast activations: single-instruction MUFU.TANH
// ---------------------------------------------------------------------------
__device__ __forceinline__ float tanha(float x) {
    float y;
    asm("tanh.approx.f32 %0, %1;" : "=f"(y) : "f"(x));
    return y;
}
__device__ __forceinline__ float fsig(float x) {
    return fmaf(tanha(0.5f * x), 0.5f, 0.5f);
}

// packed f32x2 helpers (Blackwell)
__device__ __forceinline__ u64 ffma2(u64 a, u64 b, u64 c) {
    u64 d;
    asm("fma.rn.f32x2 %0, %1, %2, %3;" : "=l"(d) : "l"(a), "l"(b), "l"(c));
    return d;
}
__device__ __forceinline__ u64 fadd2(u64 a, u64 b) {
    u64 d;
    asm("add.rn.f32x2 %0, %1, %2;" : "=l"(d) : "l"(a), "l"(b));
    return d;
}
__device__ __forceinline__ void unpk2(float& lo, float& hi, u64 v) {
    asm("mov.b64 {%0,%1}, %2;" : "=f"(lo), "=f"(hi) : "l"(v));
}

// ---------------------------------------------------------------------------
// Kernel 1: input-projection GEMM (R5 config — measured 26.7us).
// grid = (5, 64, 4): x in [0,4) -> 64-wide N tiles; x==4,y==0,z==0 -> prep.
// z = 0,1,2 -> mod0 K-chunk z; z = 3 -> mod1. BM=32,BN=64,BK=16, 256 thr,
// 2x4 microtile, double-buffered, 1 barrier/tile.
// ---------------------------------------------------------------------------
#define BKK 16
__global__ void __launch_bounds__(256) gemm_xproj(
    const float* __restrict__ x0, const float* __restrict__ Wih0,
    const float* __restrict__ bih0, const float* __restrict__ bhh0,
    const float* __restrict__ x1, const float* __restrict__ Wih1,
    const float* __restrict__ bih1, const float* __restrict__ bhh1,
    const float* __restrict__ umask, const float* __restrict__ mk) {

    if (blockIdx.x == 4) {
        if (blockIdx.y != 0 || blockIdx.z != 0) return;
        __shared__ float inv_norm[Uu];
        int tid = threadIdx.x;
        if (tid < Uu) {
            float s = 0.f;
            const float* p = mk + tid * (Ee * 2);
            #pragma unroll 8
            for (int i = 0; i < Ee * 2; i++) s += p[i] * p[i];
            inv_norm[tid] = 1.f / fmaxf(sqrtf(s), 1e-12f);
        }
        __syncthreads();
        for (int idx = tid; idx < Uu * Ee; idx += blockDim.x) {
            int u = idx >> 6;
            int e = idx & 63;
            float inv = inv_norm[u];
            g_krT[e * Uu + u] = mk[(u * Ee + e) * 2 + 0] * inv;
            g_kiT[e * Uu + u] = mk[(u * Ee + e) * 2 + 1] * inv;
        }
        return;
    }

    int z = blockIdx.z;
    bool mod1 = (z == 3);
    const float* A   = mod1 ? x1 : x0;
    const float* W   = mod1 ? Wih1 : Wih0;
    const float* bih = mod1 ? bih1 : bih0;
    const float* bhh = mod1 ? bhh1 : bhh0;
    float* out = (z == 0) ? g_xp0a : (z == 1) ? g_xp0b : (z == 2) ? g_xp0c : g_xp1;
    const int Ks = mod1 ? D1 : D0;      // row stride
    const int k0 = mod1 ? 0 : z * KC;   // chunk offset
    const bool addb = (z == 0) || mod1;

    __shared__ __align__(16) float As[2][BKK][34];   // [buf][k][m], pad 2
    __shared__ __align__(16) float Ws[2][BKK][68];   // [buf][k][n], pad 4

    int tid = threadIdx.x;
    int lk = tid & 15;          // k within tile
    int lm = tid >> 4;          // 0..15
    int bm = blockIdx.y * 32, bn = blockIdx.x * 64;

    const float* Ar0 = A + (size_t)(bm + lm) * Ks + k0;
    const float* Ar1 = Ar0 + (size_t)16 * Ks;
    const float* Wr0 = W + (size_t)(bn + lm) * Ks + k0;
    const float* Wr1 = Wr0 + (size_t)16 * Ks;
    const float* Wr2 = Wr0 + (size_t)32 * Ks;
    const float* Wr3 = Wr0 + (size_t)48 * Ks;

    const int ntiles = (KC + BKK - 1) / BKK;   // 7

    float a0 = Ar0[lk], a1 = Ar1[lk];
    float w0 = Wr0[lk], w1 = Wr1[lk], w2 = Wr2[lk], w3 = Wr3[lk];
    As[0][lk][lm] = a0;  As[0][lk][lm + 16] = a1;
    Ws[0][lk][lm] = w0;  Ws[0][lk][lm + 16] = w1;
    Ws[0][lk][lm + 32] = w2;  Ws[0][lk][lm + 48] = w3;
    __syncthreads();

    float acc[2][4] = {};
    int tx = tid & 15;          // n-quad
    int ty = tid >> 4;          // m-pair

    for (int tl = 0; tl < ntiles; tl++) {
        int cur = tl & 1;
        bool has = (tl + 1) < ntiles;
        if (has) {
            int k = (tl + 1) * BKK + lk;
            bool v = k < KC;
            a0 = v ? Ar0[k] : 0.f;  a1 = v ? Ar1[k] : 0.f;
            w0 = v ? Wr0[k] : 0.f;  w1 = v ? Wr1[k] : 0.f;
            w2 = v ? Wr2[k] : 0.f;  w3 = v ? Wr3[k] : 0.f;
        }
        #pragma unroll
        for (int kk = 0; kk < BKK; kk++) {
            float2 av = *(const float2*)&As[cur][kk][ty * 2];
            float4 wv = *(const float4*)&Ws[cur][kk][tx * 4];
            acc[0][0] += av.x * wv.x;  acc[0][1] += av.x * wv.y;
            acc[0][2] += av.x * wv.z;  acc[0][3] += av.x * wv.w;
            acc[1][0] += av.y * wv.x;  acc[1][1] += av.y * wv.y;
            acc[1][2] += av.y * wv.z;  acc[1][3] += av.y * wv.w;
        }
        if (has) {
            int nb = cur ^ 1;
            As[nb][lk][lm] = a0;  As[nb][lk][lm + 16] = a1;
            Ws[nb][lk][lm] = w0;  Ws[nb][lk][lm + 16] = w1;
            Ws[nb][lk][lm + 32] = w2;  Ws[nb][lk][lm + 48] = w3;
        }
        __syncthreads();
    }

    int n = bn + tx * 4;
    float bv0 = 0.f, bv1 = 0.f, bv2 = 0.f, bv3 = 0.f;
    if (addb) {
        bv0 = bih[n + 0] + bhh[n + 0];
        bv1 = bih[n + 1] + bhh[n + 1];
        bv2 = bih[n + 2] + bhh[n + 2];
        bv3 = bih[n + 3] + bhh[n + 3];
    }
    #pragma unroll
    for (int i = 0; i < 2; i++) {
        int m = bm + ty * 2 + i;
        float um = umask[m];
        float4 o;
        o.x = um * acc[i][0] + bv0;
        o.y = um * acc[i][1] + bv1;
        o.z = um * acc[i][2] + bv2;
        o.w = um * acc[i][3] + bv3;
        *(float4*)&out[(size_t)m * G4E + n] = o;
    }
}

// ---------------------------------------------------------------------------
// Kernel 2: LSTM recurrence. Depth-2 software pipeline on the xp chunk loads:
// at step t we issue loads for t+2; the t+1 sum uses values loaded a full
// step earlier. Loads for unused streams predicated off for mod1.
// ---------------------------------------------------------------------------
__global__ void __launch_bounds__(256, 1) lstm_kernel(
    const float* __restrict__ Whh0, const float* __restrict__ Whh1) {
    int mod = blockIdx.x >> 5;
    int b = blockIdx.x & 31;
    const float* Whh = mod ? Whh1 : Whh0;
    size_t off = (size_t)b * Tt * G4E;
    const float* xpa = (mod ? g_xp1 : g_xp0a) + off;
    const float* xpb = g_xp0b + off;
    const float* xpc = g_xp0c + off;
    float* hout = (mod ? g_h1 : g_h0) + (size_t)b * Tt * Ee;

    int tid = threadIdx.x;
    int w = tid >> 5, l = tid & 31;
    int gt = l & 3;
    int cell = w * 8 + (l >> 2);
    int r = gt * 64 + cell;

    u64 wp[32];
    {
        const float2* src = (const float2*)(Whh + (size_t)r * Ee);
        #pragma unroll
        for (int i = 0; i < 32; i++) {
            union { float2 f; u64 u; } cv;
            cv.f = src[i];
            wp[i] = cv.u;
        }
    }

    __shared__ __align__(16) float hs[2][Ee];
    if (tid < Ee) hs[0][tid] = 0.f;
    float c = 0.f;
    __syncthreads();

    // depth-2 pipelined chunk loads
    float gpre;                       // sum for step t (ready)
    float la1, lb1 = 0.f, lc1 = 0.f;  // raw loads for step t+1 (in flight)
    {
        float la = xpa[r], lb = 0.f, lc = 0.f;
        if (!mod) { lb = xpb[r]; lc = xpc[r]; }
        gpre = la + lb + lc;
        la1 = xpa[G4E + r];
        if (!mod) { lb1 = xpb[G4E + r]; lc1 = xpc[G4E + r]; }
    }

    #pragma unroll 1
    for (int t = 0; t < Tt; t++) {
        // issue loads for step t+2 (consumed 2 iterations later)
        float la2 = 0.f, lb2 = 0.f, lc2 = 0.f;
        if (t + 2 < Tt) {
            int idx = (t + 2) * G4E + r;
            la2 = xpa[idx];
            if (!mod) { lb2 = xpb[idx]; lc2 = xpc[idx]; }
        }
        // sum for step t+1 (loads issued at t-1 have had a full step to land)
        float gnext = la1 + lb1 + lc1;

        const ulonglong2* h2 = (const ulonglong2*)hs[t & 1];
        u64 a0 = 0ull, a1 = 0ull, a2 = 0ull, a3 = 0ull;
        #pragma unroll
        for (int i = 0; i < 16; i += 2) {
            ulonglong2 hv = h2[i];
            a0 = ffma2(wp[2 * i + 0], hv.x, a0);
            a1 = ffma2(wp[2 * i + 1], hv.y, a1);
            ulonglong2 hv2 = h2[i + 1];
            a2 = ffma2(wp[2 * i + 2], hv2.x, a2);
            a3 = ffma2(wp[2 * i + 3], hv2.y, a3);
        }
        u64 s = fadd2(fadd2(a0, a1), fadd2(a2, a3));
        float lo, hi;
        unpk2(lo, hi, s);
        float g = gpre + lo + hi;
        gpre = gnext;
        la1 = la2; lb1 = lb2; lc1 = lc2;

        float act = (gt == 2) ? tanha(g) : fsig(g);

        // independent gathers (depth-1 shuffle chain)
        float v1 = __shfl_xor_sync(0xffffffffu, act, 1);
        float v2 = __shfl_xor_sync(0xffffffffu, act, 2);
        float v3 = __shfl_xor_sync(0xffffffffu, act, 3);

        if (gt == 0) {
            // act=sig(i), v1=sig(f), v2=tanh(g), v3=sig(o)
            c = v1 * c + act * v2;
            float h = tanha(v3 * tanha(c));
            hs[(t + 1) & 1][cell] = h;
            hout[t * Ee + cell] = h;
        }
        __syncthreads();
    }
}

// ---------------------------------------------------------------------------
// Kernel 3: normalize + phase + measurement + MLP + log_softmax.
// 256 blocks, 8 rows each (2 groups of 4). Staged weights in smem (R5 config).
// ---------------------------------------------------------------------------
__global__ void __launch_bounds__(256) epilogue_kernel(
    const float* __restrict__ smask, const float* __restrict__ phase_table,
    const float* __restrict__ W1, const float* __restrict__ b1,
    const float* __restrict__ W2, const float* __restrict__ b2,
    float* __restrict__ out) {
    __shared__ float krT[Ee * Uu];
    __shared__ float kiT[Ee * Uu];
    __shared__ float W1s[CELL * 65];
    __shared__ float r0s[4][Ee], i0s[4][Ee], r1s[4][Ee], i1s[4][Ee];
    __shared__ float ms[4][2 * Uu];
    __shared__ float hids[4][CELL];
    __shared__ float preds[4][8];
    __shared__ float part[4][2][2];
    __shared__ int sidx[4];
    __shared__ float lse_s[4];

    int tid = threadIdx.x;
    int slot = tid >> 6;
    int lt = tid & 63;

    for (int i = tid; i < Ee * Uu; i += 256) { krT[i] = g_krT[i]; kiT[i] = g_kiT[i]; }
    for (int i = tid; i < CELL * CELL; i += 256) {
        int cc = i >> 6, k = i & 63;
        W1s[cc * 65 + k] = W1[i];
    }

    for (int grp = 0; grp < 2; grp++) {
        int row = blockIdx.x * 8 + grp * 4 + slot;

        float h0 = g_h0[row * Ee + lt];
        float h1 = g_h1[row * Ee + lt];
        float v0 = h0 * h0, v1 = h1 * h1;
        #pragma unroll
        for (int off = 16; off; off >>= 1) {
            v0 += __shfl_xor_sync(0xffffffffu, v0, off);
            v1 += __shfl_xor_sync(0xffffffffu, v1, off);
        }
        if ((tid & 31) == 0) { part[slot][lt >> 5][0] = v0; part[slot][lt >> 5][1] = v1; }
        if (lt == 0) {
            const float* sm = smask + row * Ss;
            float best = sm[0]; int bi = 0;
            #pragma unroll
            for (int e = 1; e < Ss; e++) { float v = sm[e]; if (v > best) { best = v; bi = e; } }
            sidx[slot] = bi;
        }
        __syncthreads();

        float s0 = part[slot][0][0] + part[slot][1][0];
        float s1 = part[slot][0][1] + part[slot][1][1];
        float inv0 = 1.f / fmaxf(sqrtf(s0), 1e-12f);
        float inv1 = 1.f / fmaxf(sqrtf(s1), 1e-12f);
        float n0 = h0 * inv0, n1 = h1 * inv1;

        float ph = phase_table[sidx[slot] * Ee + lt];
        float cp = cosf(ph), sp = sinf(ph);
        r0s[slot][lt] = cp * n0; i0s[slot][lt] = sp * n0;
        r1s[slot][lt] = cp * n1; i1s[slot][lt] = sp * n1;
        __syncthreads();

        {
            int mo = lt >> 5;
            int uu = lt & 31;
            const float* R = mo ? r1s[slot] : r0s[slot];
            const float* I = mo ? i1s[slot] : i0s[slot];
            float pr = 0.f, pi = 0.f;
            #pragma unroll 16
            for (int e = 0; e < Ee; e++) {
                float kr = krT[e * Uu + uu];
                float ki = kiT[e * Uu + uu];
                float rr = R[e], im = I[e];
                pr += kr * rr - ki * im;
                pi += ki * rr + kr * im;
            }
            ms[slot][lt] = pr * pr + pi * pi;
        }
        __syncthreads();

        {
            int cc = lt;
            float acc = b1[cc];
            #pragma unroll 16
            for (int k = 0; k < CELL; k++) acc += ms[slot][k] * W1s[cc * 65 + k];
            hids[slot][cc] = fmaxf(acc, 0.f);
        }
        __syncthreads();

        if (lt < Cc) {
            float acc = b2[lt];
            const float* w2 = W2 + lt * CELL;
            #pragma unroll 16
            for (int k = 0; k < CELL; k++) acc += hids[slot][k] * w2[k];
            preds[slot][lt] = tanhf(acc);
        }
        __syncthreads();

        if (lt == 0) {
            float m = preds[slot][0];
            #pragma unroll
            for (int k = 1; k < Cc; k++) m = fmaxf(m, preds[slot][k]);
            float se = 0.f;
            #pragma unroll
            for (int k = 0; k < Cc; k++) se += expf(preds[slot][k] - m);
            lse_s[slot] = m + logf(se);
        }
        __syncthreads();

        if (lt < Cc) out[row * Cc + lt] = preds[slot][lt] - lse_s[slot];
        __syncthreads();
    }
}

// ---------------------------------------------------------------------------
extern "C" void kernel_launch(void* const* d_in, const int* in_sizes, int n_in,
                              void* d_out, int out_size) {
    const float* x0        = (const float*)d_in[0];
    const float* x1        = (const float*)d_in[1];
    const float* smask     = (const float*)d_in[2];
    const float* umask     = (const float*)d_in[3];
    const float* W_ih0     = (const float*)d_in[4];
    const float* W_hh0     = (const float*)d_in[5];
    const float* b_ih0     = (const float*)d_in[6];
    const float* b_hh0     = (const float*)d_in[7];
    const float* W_ih1     = (const float*)d_in[8];
    const float* W_hh1     = (const float*)d_in[9];
    const float* b_ih1     = (const float*)d_in[10];
    const float* b_hh1     = (const float*)d_in[11];
    const float* phase_tab = (const float*)d_in[12];
    const float* meas_k    = (const float*)d_in[13];
    const float* W1        = (const float*)d_in[14];
    const float* b1        = (const float*)d_in[15];
    const float* W2        = (const float*)d_in[16];
    const float* b2        = (const float*)d_in[17];
    float* out = (float*)d_out;

    dim3 ggrid(5, ROWS / 32, 4);   // (5, 64, 4): 3 mod0 chunks + mod1, uniform K=100
    gemm_xproj<<<ggrid, 256>>>(x0, W_ih0, b_ih0, b_hh0,
                               x1, W_ih1, b_ih1, b_hh1, umask, meas_k);

    lstm_kernel<<<64, 256>>>(W_hh0, W_hh1);

    epilogue_kernel<<<ROWS / 8, 256>>>(smask, phase_tab, W1, b1, W2, b2, out);
}

// round 8
// speedup vs baseline: 1.5242x; 1.1455x over previous
#include <cuda_runtime.h>
#include <math.h>
#include <stdint.h>

// Problem constants
#define Bb 32
#define Tt 64
#define Ee 64
#define Uu 32
#define D0 300
#define D1 100
#define Ss 9
#define CELL 64
#define Cc 6
#define ROWS (Bb*Tt)      // 2048
#define G4E (4*Ee)        // 256
#define KC 100            // uniform K-chunk

// Device scratch: mod0 xproj split into 3 K-chunk partials (a gets the sum)
__device__ float g_xp0a[ROWS * G4E];
__device__ float g_xp0b[ROWS * G4E];
__device__ float g_xp0c[ROWS * G4E];
__device__ float g_xp1 [ROWS * G4E];
__device__ float g_h0[ROWS * Ee];
__device__ float g_h1[ROWS * Ee];
__device__ float g_krT[Ee * Uu];   // [e][u]
__device__ float g_kiT[Ee * Uu];

typedef unsigned long long u64;

// ---------------------------------------------------------------------------
// fast activations: single-instruction MUFU.TANH
// ---------------------------------------------------------------------------
__device__ __forceinline__ float tanha(float x) {
    float y;
    asm("tanh.approx.f32 %0, %1;" : "=f"(y) : "f"(x));
    return y;
}
__device__ __forceinline__ float fsig(float x) {
    return fmaf(tanha(0.5f * x), 0.5f, 0.5f);
}

// packed f32x2 helpers (Blackwell)
__device__ __forceinline__ u64 ffma2(u64 a, u64 b, u64 c) {
    u64 d;
    asm("fma.rn.f32x2 %0, %1, %2, %3;" : "=l"(d) : "l"(a), "l"(b), "l"(c));
    return d;
}
__device__ __forceinline__ u64 fadd2(u64 a, u64 b) {
    u64 d;
    asm("add.rn.f32x2 %0, %1, %2;" : "=l"(d) : "l"(a), "l"(b));
    return d;
}
__device__ __forceinline__ void unpk2(float& lo, float& hi, u64 v) {
    asm("mov.b64 {%0,%1}, %2;" : "=f"(lo), "=f"(hi) : "l"(v));
}

// ---------------------------------------------------------------------------
// Kernel 1: input-projection GEMM (R5 config — measured 26.7us).
// grid = (5, 64, 4): x in [0,4) -> 64-wide N tiles; x==4,y==0,z==0 -> prep.
// z = 0,1,2 -> mod0 K-chunk z; z = 3 -> mod1. BM=32,BN=64,BK=16, 256 thr,
// 2x4 microtile, double-buffered, 1 barrier/tile.
// ---------------------------------------------------------------------------
#define BKK 16
__global__ void __launch_bounds__(256) gemm_xproj(
    const float* __restrict__ x0, const float* __restrict__ Wih0,
    const float* __restrict__ bih0, const float* __restrict__ bhh0,
    const float* __restrict__ x1, const float* __restrict__ Wih1,
    const float* __restrict__ bih1, const float* __restrict__ bhh1,
    const float* __restrict__ umask, const float* __restrict__ mk) {

    if (blockIdx.x == 4) {
        if (blockIdx.y != 0 || blockIdx.z != 0) return;
        __shared__ float inv_norm[Uu];
        int tid = threadIdx.x;
        if (tid < Uu) {
            float s = 0.f;
            const float* p = mk + tid * (Ee * 2);
            #pragma unroll 8
            for (int i = 0; i < Ee * 2; i++) s += p[i] * p[i];
            inv_norm[tid] = 1.f / fmaxf(sqrtf(s), 1e-12f);
        }
        __syncthreads();
        for (int idx = tid; idx < Uu * Ee; idx += blockDim.x) {
            int u = idx >> 6;
            int e = idx & 63;
            float inv = inv_norm[u];
            g_krT[e * Uu + u] = mk[(u * Ee + e) * 2 + 0] * inv;
            g_kiT[e * Uu + u] = mk[(u * Ee + e) * 2 + 1] * inv;
        }
        return;
    }

    int z = blockIdx.z;
    bool mod1 = (z == 3);
    const float* A   = mod1 ? x1 : x0;
    const float* W   = mod1 ? Wih1 : Wih0;
    const float* bih = mod1 ? bih1 : bih0;
    const float* bhh = mod1 ? bhh1 : bhh0;
    float* out = (z == 0) ? g_xp0a : (z == 1) ? g_xp0b : (z == 2) ? g_xp0c : g_xp1;
    const int Ks = mod1 ? D1 : D0;      // row stride
    const int k0 = mod1 ? 0 : z * KC;   // chunk offset
    const bool addb = (z == 0) || mod1;

    __shared__ __align__(16) float As[2][BKK][34];   // [buf][k][m], pad 2
    __shared__ __align__(16) float Ws[2][BKK][68];   // [buf][k][n], pad 4

    int tid = threadIdx.x;
    int lk = tid & 15;          // k within tile
    int lm = tid >> 4;          // 0..15
    int bm = blockIdx.y * 32, bn = blockIdx.x * 64;

    const float* Ar0 = A + (size_t)(bm + lm) * Ks + k0;
    const float* Ar1 = Ar0 + (size_t)16 * Ks;
    const float* Wr0 = W + (size_t)(bn + lm) * Ks + k0;
    const float* Wr1 = Wr0 + (size_t)16 * Ks;
    const float* Wr2 = Wr0 + (size_t)32 * Ks;
    const float* Wr3 = Wr0 + (size_t)48 * Ks;

    const int ntiles = (KC + BKK - 1) / BKK;   // 7

    float a0 = Ar0[lk], a1 = Ar1[lk];
    float w0 = Wr0[lk], w1 = Wr1[lk], w2 = Wr2[lk], w3 = Wr3[lk];
    As[0][lk][lm] = a0;  As[0][lk][lm + 16] = a1;
    Ws[0][lk][lm] = w0;  Ws[0][lk][lm + 16] = w1;
    Ws[0][lk][lm + 32] = w2;  Ws[0][lk][lm + 48] = w3;
    __syncthreads();

    float acc[2][4] = {};
    int tx = tid & 15;          // n-quad
    int ty = tid >> 4;          // m-pair

    for (int tl = 0; tl < ntiles; tl++) {
        int cur = tl & 1;
        bool has = (tl + 1) < ntiles;
        if (has) {
            int k = (tl + 1) * BKK + lk;
            bool v = k < KC;
            a0 = v ? Ar0[k] : 0.f;  a1 = v ? Ar1[k] : 0.f;
            w0 = v ? Wr0[k] : 0.f;  w1 = v ? Wr1[k] : 0.f;
            w2 = v ? Wr2[k] : 0.f;  w3 = v ? Wr3[k] : 0.f;
        }
        #pragma unroll
        for (int kk = 0; kk < BKK; kk++) {
            float2 av = *(const float2*)&As[cur][kk][ty * 2];
            float4 wv = *(const float4*)&Ws[cur][kk][tx * 4];
            acc[0][0] += av.x * wv.x;  acc[0][1] += av.x * wv.y;
            acc[0][2] += av.x * wv.z;  acc[0][3] += av.x * wv.w;
            acc[1][0] += av.y * wv.x;  acc[1][1] += av.y * wv.y;
            acc[1][2] += av.y * wv.z;  acc[1][3] += av.y * wv.w;
        }
        if (has) {
            int nb = cur ^ 1;
            As[nb][lk][lm] = a0;  As[nb][lk][lm + 16] = a1;
            Ws[nb][lk][lm] = w0;  Ws[nb][lk][lm + 16] = w1;
            Ws[nb][lk][lm + 32] = w2;  Ws[nb][lk][lm + 48] = w3;
        }
        __syncthreads();
    }

    int n = bn + tx * 4;
    float bv0 = 0.f, bv1 = 0.f, bv2 = 0.f, bv3 = 0.f;
    if (addb) {
        bv0 = bih[n + 0] + bhh[n + 0];
        bv1 = bih[n + 1] + bhh[n + 1];
        bv2 = bih[n + 2] + bhh[n + 2];
        bv3 = bih[n + 3] + bhh[n + 3];
    }
    #pragma unroll
    for (int i = 0; i < 2; i++) {
        int m = bm + ty * 2 + i;
        float um = umask[m];
        float4 o;
        o.x = um * acc[i][0] + bv0;
        o.y = um * acc[i][1] + bv1;
        o.z = um * acc[i][2] + bv2;
        o.w = um * acc[i][3] + bv3;
        *(float4*)&out[(size_t)m * G4E + n] = o;
    }
}

// ---------------------------------------------------------------------------
// Kernel 1.5: reduce mod0 chunk partials into g_xp0a (float4, elementwise).
// 524288 floats = 131072 float4 -> 512 blocks x 256 threads.
// ---------------------------------------------------------------------------
__global__ void __launch_bounds__(256) reduce_xp0() {
    int i = blockIdx.x * blockDim.x + threadIdx.x;
    float4 a = ((const float4*)g_xp0a)[i];
    float4 b = ((const float4*)g_xp0b)[i];
    float4 c = ((const float4*)g_xp0c)[i];
    a.x += b.x + c.x;
    a.y += b.y + c.y;
    a.z += b.z + c.z;
    a.w += b.w + c.w;
    ((float4*)g_xp0a)[i] = a;
}

// ---------------------------------------------------------------------------
// Kernel 2: LSTM recurrence — single xp stream, depth-1 prefetch, shuffle
// gather, double-buffered h, one barrier per step, MUFU.TANH.
// ---------------------------------------------------------------------------
__global__ void __launch_bounds__(256, 1) lstm_kernel(
    const float* __restrict__ Whh0, const float* __restrict__ Whh1) {
    int mod = blockIdx.x >> 5;
    int b = blockIdx.x & 31;
    const float* Whh = mod ? Whh1 : Whh0;
    const float* xp = (mod ? g_xp1 : g_xp0a) + (size_t)b * Tt * G4E;
    float* hout = (mod ? g_h1 : g_h0) + (size_t)b * Tt * Ee;

    int tid = threadIdx.x;
    int w = tid >> 5, l = tid & 31;
    int gt = l & 3;
    int cell = w * 8 + (l >> 2);
    int r = gt * 64 + cell;

    u64 wp[32];
    {
        const float2* src = (const float2*)(Whh + (size_t)r * Ee);
        #pragma unroll
        for (int i = 0; i < 32; i++) {
            union { float2 f; u64 u; } cv;
            cv.f = src[i];
            wp[i] = cv.u;
        }
    }

    __shared__ __align__(16) float hs[2][Ee];
    if (tid < Ee) hs[0][tid] = 0.f;
    float c = 0.f;
    __syncthreads();

    float gpre = xp[r];
    #pragma unroll 1
    for (int t = 0; t < Tt; t++) {
        float gnext = (t + 1 < Tt) ? xp[(t + 1) * G4E + r] : 0.f;  // prefetch

        const ulonglong2* h2 = (const ulonglong2*)hs[t & 1];
        u64 a0 = 0ull, a1 = 0ull, a2 = 0ull, a3 = 0ull;
        #pragma unroll
        for (int i = 0; i < 16; i += 2) {
            ulonglong2 hv = h2[i];
            a0 = ffma2(wp[2 * i + 0], hv.x, a0);
            a1 = ffma2(wp[2 * i + 1], hv.y, a1);
            ulonglong2 hv2 = h2[i + 1];
            a2 = ffma2(wp[2 * i + 2], hv2.x, a2);
            a3 = ffma2(wp[2 * i + 3], hv2.y, a3);
        }
        u64 s = fadd2(fadd2(a0, a1), fadd2(a2, a3));
        float lo, hi;
        unpk2(lo, hi, s);
        float g = gpre + lo + hi;
        gpre = gnext;

        float act = (gt == 2) ? tanha(g) : fsig(g);

        // independent gathers within the 4-lane group
        float v1 = __shfl_xor_sync(0xffffffffu, act, 1);
        float v2 = __shfl_xor_sync(0xffffffffu, act, 2);
        float v3 = __shfl_xor_sync(0xffffffffu, act, 3);

        if (gt == 0) {
            // act=sig(i), v1=sig(f), v2=tanh(g), v3=sig(o)
            c = v1 * c + act * v2;
            float h = tanha(v3 * tanha(c));
            hs[(t + 1) & 1][cell] = h;
            hout[t * Ee + cell] = h;
        }
        __syncthreads();
    }
}

// ---------------------------------------------------------------------------
// Kernel 3: normalize + phase + measurement + MLP + log_softmax.
// 256 blocks, 8 rows each (2 groups of 4). Staged weights in smem.
// ---------------------------------------------------------------------------
__global__ void __launch_bounds__(256) epilogue_kernel(
    const float* __restrict__ smask, const float* __restrict__ phase_table,
    const float* __restrict__ W1, const float* __restrict__ b1,
    const float* __restrict__ W2, const float* __restrict__ b2,
    float* __restrict__ out) {
    __shared__ float krT[Ee * Uu];
    __shared__ float kiT[Ee * Uu];
    __shared__ float W1s[CELL * 65];
    __shared__ float r0s[4][Ee], i0s[4][Ee], r1s[4][Ee], i1s[4][Ee];
    __shared__ float ms[4][2 * Uu];
    __shared__ float hids[4][CELL];
    __shared__ float preds[4][8];
    __shared__ float part[4][2][2];
    __shared__ int sidx[4];
    __shared__ float lse_s[4];

    int tid = threadIdx.x;
    int slot = tid >> 6;
    int lt = tid & 63;

    for (int i = tid; i < Ee * Uu; i += 256) { krT[i] = g_krT[i]; kiT[i] = g_kiT[i]; }
    for (int i = tid; i < CELL * CELL; i += 256) {
        int cc = i >> 6, k = i & 63;
        W1s[cc * 65 + k] = W1[i];
    }

    for (int grp = 0; grp < 2; grp++) {
        int row = blockIdx.x * 8 + grp * 4 + slot;

        float h0 = g_h0[row * Ee + lt];
        float h1 = g_h1[row * Ee + lt];
        float v0 = h0 * h0, v1 = h1 * h1;
        #pragma unroll
        for (int off = 16; off; off >>= 1) {
            v0 += __shfl_xor_sync(0xffffffffu, v0, off);
            v1 += __shfl_xor_sync(0xffffffffu, v1, off);
        }
        if ((tid & 31) == 0) { part[slot][lt >> 5][0] = v0; part[slot][lt >> 5][1] = v1; }
        if (lt == 0) {
            const float* sm = smask + row * Ss;
            float best = sm[0]; int bi = 0;
            #pragma unroll
            for (int e = 1; e < Ss; e++) { float v = sm[e]; if (v > best) { best = v; bi = e; } }
            sidx[slot] = bi;
        }
        __syncthreads();

        float s0 = part[slot][0][0] + part[slot][1][0];
        float s1 = part[slot][0][1] + part[slot][1][1];
        float inv0 = 1.f / fmaxf(sqrtf(s0), 1e-12f);
        float inv1 = 1.f / fmaxf(sqrtf(s1), 1e-12f);
        float n0 = h0 * inv0, n1 = h1 * inv1;

        float ph = phase_table[sidx[slot] * Ee + lt];
        float cp = cosf(ph), sp = sinf(ph);
        r0s[slot][lt] = cp * n0; i0s[slot][lt] = sp * n0;
        r1s[slot][lt] = cp * n1; i1s[slot][lt] = sp * n1;
        __syncthreads();

        {
            int mo = lt >> 5;
            int uu = lt & 31;
            const float* R = mo ? r1s[slot] : r0s[slot];
            const float* I = mo ? i1s[slot] : i0s[slot];
            float pr = 0.f, pi = 0.f;
            #pragma unroll 16
            for (int e = 0; e < Ee; e++) {
                float kr = krT[e * Uu + uu];
                float ki = kiT[e * Uu + uu];
                float rr = R[e], im = I[e];
                pr += kr * rr - ki * im;
                pi += ki * rr + kr * im;
            }
            ms[slot][lt] = pr * pr + pi * pi;
        }
        __syncthreads();

        {
            int cc = lt;
            float acc = b1[cc];
            #pragma unroll 16
            for (int k = 0; k < CELL; k++) acc += ms[slot][k] * W1s[cc * 65 + k];
            hids[slot][cc] = fmaxf(acc, 0.f);
        }
        __syncthreads();

        if (lt < Cc) {
            float acc = b2[lt];
            const float* w2 = W2 + lt * CELL;
            #pragma unroll 16
            for (int k = 0; k < CELL; k++) acc += hids[slot][k] * w2[k];
            preds[slot][lt] = tanhf(acc);
        }
        __syncthreads();

        if (lt == 0) {
            float m = preds[slot][0];
            #pragma unroll
            for (int k = 1; k < Cc; k++) m = fmaxf(m, preds[slot][k]);
            float se = 0.f;
            #pragma unroll
            for (int k = 0; k < Cc; k++) se += expf(preds[slot][k] - m);
            lse_s[slot] = m + logf(se);
        }
        __syncthreads();

        if (lt < Cc) out[row * Cc + lt] = preds[slot][lt] - lse_s[slot];
        __syncthreads();
    }
}

// ---------------------------------------------------------------------------
extern "C" void kernel_launch(void* const* d_in, const int* in_sizes, int n_in,
                              void* d_out, int out_size) {
    const float* x0        = (const float*)d_in[0];
    const float* x1        = (const float*)d_in[1];
    const float* smask     = (const float*)d_in[2];
    const float* umask     = (const float*)d_in[3];
    const float* W_ih0     = (const float*)d_in[4];
    const float* W_hh0     = (const float*)d_in[5];
    const float* b_ih0     = (const float*)d_in[6];
    const float* b_hh0     = (const float*)d_in[7];
    const float* W_ih1     = (const float*)d_in[8];
    const float* W_hh1     = (const float*)d_in[9];
    const float* b_ih1     = (const float*)d_in[10];
    const float* b_hh1     = (const float*)d_in[11];
    const float* phase_tab = (const float*)d_in[12];
    const float* meas_k    = (const float*)d_in[13];
    const float* W1        = (const float*)d_in[14];
    const float* b1        = (const float*)d_in[15];
    const float* W2        = (const float*)d_in[16];
    const float* b2        = (const float*)d_in[17];
    float* out = (float*)d_out;

    dim3 ggrid(5, ROWS / 32, 4);   // (5, 64, 4): 3 mod0 chunks + mod1, uniform K=100
    gemm_xproj<<<ggrid, 256>>>(x0, W_ih0, b_ih0, b_hh0,
                               x1, W_ih1, b_ih1, b_hh1, umask, meas_k);

    reduce_xp0<<<ROWS * G4E / 4 / 256, 256>>>();

    lstm_kernel<<<64, 256>>>(W_hh0, W_hh1);

    epilogue_kernel<<<ROWS / 8, 256>>>(smask, phase_tab, W1, b1, W2, b2, out);
}

// round 9
// speedup vs baseline: 1.6159x; 1.0602x over previous
#include <cuda_runtime.h>
#include <math.h>
#include <stdint.h>

// Problem constants
#define Bb 32
#define Tt 64
#define Ee 64
#define Uu 32
#define D0 300
#define D1 100
#define Ss 9
#define CELL 64
#define Cc 6
#define ROWS (Bb*Tt)      // 2048
#define G4E (4*Ee)        // 256
#define KC 100            // uniform K-chunk

// Device scratch: mod0 xproj split into 3 K-chunk partials (a gets the sum)
__device__ float g_xp0a[ROWS * G4E];
__device__ float g_xp0b[ROWS * G4E];
__device__ float g_xp0c[ROWS * G4E];
__device__ float g_xp1 [ROWS * G4E];
__device__ float g_h0[ROWS * Ee];
__device__ float g_h1[ROWS * Ee];
__device__ float g_krT[Ee * Uu];   // [e][u]
__device__ float g_kiT[Ee * Uu];

typedef unsigned long long u64;

// ---------------------------------------------------------------------------
// fast activations: single-instruction MUFU.TANH
// ---------------------------------------------------------------------------
__device__ __forceinline__ float tanha(float x) {
    float y;
    asm("tanh.approx.f32 %0, %1;" : "=f"(y) : "f"(x));
    return y;
}
__device__ __forceinline__ float fsig(float x) {
    return fmaf(tanha(0.5f * x), 0.5f, 0.5f);
}

// packed f32x2 helpers (Blackwell)
__device__ __forceinline__ u64 ffma2(u64 a, u64 b, u64 c) {
    u64 d;
    asm("fma.rn.f32x2 %0, %1, %2, %3;" : "=l"(d) : "l"(a), "l"(b), "l"(c));
    return d;
}
__device__ __forceinline__ u64 fadd2(u64 a, u64 b) {
    u64 d;
    asm("add.rn.f32x2 %0, %1, %2;" : "=l"(d) : "l"(a), "l"(b));
    return d;
}
__device__ __forceinline__ void unpk2(float& lo, float& hi, u64 v) {
    asm("mov.b64 {%0,%1}, %2;" : "=f"(lo), "=f"(hi) : "l"(v));
}

// ---------------------------------------------------------------------------
// Kernel 1: input-projection GEMM (measured-best config).
// grid = (5, 64, 4): x in [0,4) -> 64-wide N tiles; x==4,y==0,z==0 -> prep.
// z = 0,1,2 -> mod0 K-chunk z; z = 3 -> mod1. BM=32,BN=64,BK=16, 256 thr,
// 2x4 microtile, double-buffered, 1 barrier/tile.
// ---------------------------------------------------------------------------
#define BKK 16
__global__ void __launch_bounds__(256) gemm_xproj(
    const float* __restrict__ x0, const float* __restrict__ Wih0,
    const float* __restrict__ bih0, const float* __restrict__ bhh0,
    const float* __restrict__ x1, const float* __restrict__ Wih1,
    const float* __restrict__ bih1, const float* __restrict__ bhh1,
    const float* __restrict__ umask, const float* __restrict__ mk) {

    if (blockIdx.x == 4) {
        if (blockIdx.y != 0 || blockIdx.z != 0) return;
        __shared__ float inv_norm[Uu];
        int tid = threadIdx.x;
        if (tid < Uu) {
            float s = 0.f;
            const float* p = mk + tid * (Ee * 2);
            #pragma unroll 8
            for (int i = 0; i < Ee * 2; i++) s += p[i] * p[i];
            inv_norm[tid] = 1.f / fmaxf(sqrtf(s), 1e-12f);
        }
        __syncthreads();
        for (int idx = tid; idx < Uu * Ee; idx += blockDim.x) {
            int u = idx >> 6;
            int e = idx & 63;
            float inv = inv_norm[u];
            g_krT[e * Uu + u] = mk[(u * Ee + e) * 2 + 0] * inv;
            g_kiT[e * Uu + u] = mk[(u * Ee + e) * 2 + 1] * inv;
        }
        return;
    }

    int z = blockIdx.z;
    bool mod1 = (z == 3);
    const float* A   = mod1 ? x1 : x0;
    const float* W   = mod1 ? Wih1 : Wih0;
    const float* bih = mod1 ? bih1 : bih0;
    const float* bhh = mod1 ? bhh1 : bhh0;
    float* out = (z == 0) ? g_xp0a : (z == 1) ? g_xp0b : (z == 2) ? g_xp0c : g_xp1;
    const int Ks = mod1 ? D1 : D0;      // row stride
    const int k0 = mod1 ? 0 : z * KC;   // chunk offset
    const bool addb = (z == 0) || mod1;

    __shared__ __align__(16) float As[2][BKK][34];   // [buf][k][m], pad 2
    __shared__ __align__(16) float Ws[2][BKK][68];   // [buf][k][n], pad 4

    int tid = threadIdx.x;
    int lk = tid & 15;          // k within tile
    int lm = tid >> 4;          // 0..15
    int bm = blockIdx.y * 32, bn = blockIdx.x * 64;

    const float* Ar0 = A + (size_t)(bm + lm) * Ks + k0;
    const float* Ar1 = Ar0 + (size_t)16 * Ks;
    const float* Wr0 = W + (size_t)(bn + lm) * Ks + k0;
    const float* Wr1 = Wr0 + (size_t)16 * Ks;
    const float* Wr2 = Wr0 + (size_t)32 * Ks;
    const float* Wr3 = Wr0 + (size_t)48 * Ks;

    const int ntiles = (KC + BKK - 1) / BKK;   // 7

    float a0 = Ar0[lk], a1 = Ar1[lk];
    float w0 = Wr0[lk], w1 = Wr1[lk], w2 = Wr2[lk], w3 = Wr3[lk];
    As[0][lk][lm] = a0;  As[0][lk][lm + 16] = a1;
    Ws[0][lk][lm] = w0;  Ws[0][lk][lm + 16] = w1;
    Ws[0][lk][lm + 32] = w2;  Ws[0][lk][lm + 48] = w3;
    __syncthreads();

    float acc[2][4] = {};
    int tx = tid & 15;          // n-quad
    int ty = tid >> 4;          // m-pair

    for (int tl = 0; tl < ntiles; tl++) {
        int cur = tl & 1;
        bool has = (tl + 1) < ntiles;
        if (has) {
            int k = (tl + 1) * BKK + lk;
            bool v = k < KC;
            a0 = v ? Ar0[k] : 0.f;  a1 = v ? Ar1[k] : 0.f;
            w0 = v ? Wr0[k] : 0.f;  w1 = v ? Wr1[k] : 0.f;
            w2 = v ? Wr2[k] : 0.f;  w3 = v ? Wr3[k] : 0.f;
        }
        #pragma unroll
        for (int kk = 0; kk < BKK; kk++) {
            float2 av = *(const float2*)&As[cur][kk][ty * 2];
            float4 wv = *(const float4*)&Ws[cur][kk][tx * 4];
            acc[0][0] += av.x * wv.x;  acc[0][1] += av.x * wv.y;
            acc[0][2] += av.x * wv.z;  acc[0][3] += av.x * wv.w;
            acc[1][0] += av.y * wv.x;  acc[1][1] += av.y * wv.y;
            acc[1][2] += av.y * wv.z;  acc[1][3] += av.y * wv.w;
        }
        if (has) {
            int nb = cur ^ 1;
            As[nb][lk][lm] = a0;  As[nb][lk][lm + 16] = a1;
            Ws[nb][lk][lm] = w0;  Ws[nb][lk][lm + 16] = w1;
            Ws[nb][lk][lm + 32] = w2;  Ws[nb][lk][lm + 48] = w3;
        }
        __syncthreads();
    }

    int n = bn + tx * 4;
    float bv0 = 0.f, bv1 = 0.f, bv2 = 0.f, bv3 = 0.f;
    if (addb) {
        bv0 = bih[n + 0] + bhh[n + 0];
        bv1 = bih[n + 1] + bhh[n + 1];
        bv2 = bih[n + 2] + bhh[n + 2];
        bv3 = bih[n + 3] + bhh[n + 3];
    }
    #pragma unroll
    for (int i = 0; i < 2; i++) {
        int m = bm + ty * 2 + i;
        float um = umask[m];
        float4 o;
        o.x = um * acc[i][0] + bv0;
        o.y = um * acc[i][1] + bv1;
        o.z = um * acc[i][2] + bv2;
        o.w = um * acc[i][3] + bv3;
        *(float4*)&out[(size_t)m * G4E + n] = o;
    }
}

// ---------------------------------------------------------------------------
// Kernel 1.5: reduce mod0 chunk partials into g_xp0a (float4, elementwise).
// ---------------------------------------------------------------------------
__global__ void __launch_bounds__(256) reduce_xp0() {
    int i = blockIdx.x * blockDim.x + threadIdx.x;
    float4 a = ((const float4*)g_xp0a)[i];
    float4 b = ((const float4*)g_xp0b)[i];
    float4 c = ((const float4*)g_xp0c)[i];
    a.x += b.x + c.x;
    a.y += b.y + c.y;
    a.z += b.z + c.z;
    a.w += b.w + c.w;
    ((float4*)g_xp0a)[i] = a;
}

// ---------------------------------------------------------------------------
// Kernel 2: LSTM recurrence — single xp stream, depth-1 prefetch, shuffle
// gather, double-buffered h, one barrier per step, MUFU.TANH.
// ---------------------------------------------------------------------------
__global__ void __launch_bounds__(256, 1) lstm_kernel(
    const float* __restrict__ Whh0, const float* __restrict__ Whh1) {
    int mod = blockIdx.x >> 5;
    int b = blockIdx.x & 31;
    const float* Whh = mod ? Whh1 : Whh0;
    const float* xp = (mod ? g_xp1 : g_xp0a) + (size_t)b * Tt * G4E;
    float* hout = (mod ? g_h1 : g_h0) + (size_t)b * Tt * Ee;

    int tid = threadIdx.x;
    int w = tid >> 5, l = tid & 31;
    int gt = l & 3;
    int cell = w * 8 + (l >> 2);
    int r = gt * 64 + cell;

    u64 wp[32];
    {
        const float2* src = (const float2*)(Whh + (size_t)r * Ee);
        #pragma unroll
        for (int i = 0; i < 32; i++) {
            union { float2 f; u64 u; } cv;
            cv.f = src[i];
            wp[i] = cv.u;
        }
    }

    __shared__ __align__(16) float hs[2][Ee];
    if (tid < Ee) hs[0][tid] = 0.f;
    float c = 0.f;
    __syncthreads();

    float gpre = xp[r];
    #pragma unroll 1
    for (int t = 0; t < Tt; t++) {
        float gnext = (t + 1 < Tt) ? xp[(t + 1) * G4E + r] : 0.f;  // prefetch

        const ulonglong2* h2 = (const ulonglong2*)hs[t & 1];
        u64 a0 = 0ull, a1 = 0ull, a2 = 0ull, a3 = 0ull;
        #pragma unroll
        for (int i = 0; i < 16; i += 2) {
            ulonglong2 hv = h2[i];
            a0 = ffma2(wp[2 * i + 0], hv.x, a0);
            a1 = ffma2(wp[2 * i + 1], hv.y, a1);
            ulonglong2 hv2 = h2[i + 1];
            a2 = ffma2(wp[2 * i + 2], hv2.x, a2);
            a3 = ffma2(wp[2 * i + 3], hv2.y, a3);
        }
        u64 s = fadd2(fadd2(a0, a1), fadd2(a2, a3));
        float lo, hi;
        unpk2(lo, hi, s);
        float g = gpre + lo + hi;
        gpre = gnext;

        float act = (gt == 2) ? tanha(g) : fsig(g);

        float v1 = __shfl_xor_sync(0xffffffffu, act, 1);
        float v2 = __shfl_xor_sync(0xffffffffu, act, 2);
        float v3 = __shfl_xor_sync(0xffffffffu, act, 3);

        if (gt == 0) {
            // act=sig(i), v1=sig(f), v2=tanh(g), v3=sig(o)
            c = v1 * c + act * v2;
            float h = tanha(v3 * tanha(c));
            hs[(t + 1) & 1][cell] = h;
            hout[t * Ee + cell] = h;
        }
        __syncthreads();
    }
}

// ---------------------------------------------------------------------------
// Kernel 3: warp-per-row epilogue. 256 blocks x 8 warps; each warp owns one
// row end-to-end (norm, argmax, phase, measurement, MLP, log_softmax) with
// NO block barriers after weight staging. Lane u computes measurement u for
// both modalities; lanes (l, l+32) handle MLP1 columns; lanes 0-5 do MLP2.
// ---------------------------------------------------------------------------
__global__ void __launch_bounds__(256) epilogue_kernel(
    const float* __restrict__ smask, const float* __restrict__ phase_table,
    const float* __restrict__ W1, const float* __restrict__ b1,
    const float* __restrict__ W2, const float* __restrict__ b2,
    float* __restrict__ out) {
    __shared__ float krT[Ee * Uu];       // [e][u]  8KB
    __shared__ float kiT[Ee * Uu];       //         8KB
    __shared__ float W1s[CELL * 65];     // padded  16.6KB
    __shared__ float W2s[Cc * 65];       // padded  1.5KB
    __shared__ float rs0[8][Ee], is0[8][Ee], rs1[8][Ee], is1[8][Ee];
    __shared__ float msS[8][2 * Uu];
    __shared__ float hidS[8][CELL];

    int tid = threadIdx.x;
    int wid = tid >> 5;
    int lane = tid & 31;

    // stage shared weights once per block
    for (int i = tid; i < Ee * Uu; i += 256) { krT[i] = g_krT[i]; kiT[i] = g_kiT[i]; }
    for (int i = tid; i < CELL * CELL; i += 256)
        W1s[(i >> 6) * 65 + (i & 63)] = W1[i];
    for (int i = tid; i < Cc * CELL; i += 256)
        W2s[(i >> 6) * 65 + (i & 63)] = W2[i];
    __syncthreads();

    int row = blockIdx.x * 8 + wid;

    // ---- load h (each lane holds e=lane and e=lane+32), norms via shuffle
    const float* h0p = g_h0 + (size_t)row * Ee;
    const float* h1p = g_h1 + (size_t)row * Ee;
    float h0a = h0p[lane], h0b = h0p[lane + 32];
    float h1a = h1p[lane], h1b = h1p[lane + 32];
    float v0 = h0a * h0a + h0b * h0b;
    float v1 = h1a * h1a + h1b * h1b;
    #pragma unroll
    for (int off = 16; off; off >>= 1) {
        v0 += __shfl_xor_sync(0xffffffffu, v0, off);
        v1 += __shfl_xor_sync(0xffffffffu, v1, off);
    }
    float inv0 = 1.f / fmaxf(sqrtf(v0), 1e-12f);
    float inv1 = 1.f / fmaxf(sqrtf(v1), 1e-12f);

    // ---- argmax over smask (first max wins) via butterfly
    float av = (lane < Ss) ? smask[row * Ss + lane] : -1e30f;
    int ai = lane;
    #pragma unroll
    for (int off = 16; off; off >>= 1) {
        float ov = __shfl_xor_sync(0xffffffffu, av, off);
        int oi = __shfl_xor_sync(0xffffffffu, ai, off);
        if (ov > av || (ov == av && oi < ai)) { av = ov; ai = oi; }
    }
    int sidx = ai;

    // ---- phase rotation; stash r/i vectors in per-warp smem
    const float* php = phase_table + sidx * Ee;
    float pha = php[lane], phb = php[lane + 32];
    float cpa, spa, cpb, spb;
    __sincosf(pha, &spa, &cpa);
    __sincosf(phb, &spb, &cpb);
    float n0a = h0a * inv0, n0b = h0b * inv0;
    float n1a = h1a * inv1, n1b = h1b * inv1;
    rs0[wid][lane] = cpa * n0a;  rs0[wid][lane + 32] = cpb * n0b;
    is0[wid][lane] = spa * n0a;  is0[wid][lane + 32] = spb * n0b;
    rs1[wid][lane] = cpa * n1a;  rs1[wid][lane + 32] = cpb * n1b;
    is1[wid][lane] = spa * n1a;  is1[wid][lane + 32] = spb * n1b;
    __syncwarp();

    // ---- measurement: lane u computes m[u] (mod0) and m[32+u] (mod1)
    {
        float pr0 = 0.f, pi0 = 0.f, pr1 = 0.f, pi1 = 0.f;
        #pragma unroll 8
        for (int e = 0; e < Ee; e++) {
            float kr = krT[e * Uu + lane];
            float ki = kiT[e * Uu + lane];
            float r0 = rs0[wid][e], i0 = is0[wid][e];
            float r1 = rs1[wid][e], i1 = is1[wid][e];
            pr0 += kr * r0 - ki * i0;  pi0 += ki * r0 + kr * i0;
            pr1 += kr * r1 - ki * i1;  pi1 += ki * r1 + kr * i1;
        }
        msS[wid][lane]      = pr0 * pr0 + pi0 * pi0;
        msS[wid][lane + 32] = pr1 * pr1 + pi1 * pi1;
    }
    __syncwarp();

    // ---- MLP1: lane handles columns lane and lane+32
    {
        float acc0 = b1[lane], acc1 = b1[lane + 32];
        const float* w1a = &W1s[lane * 65];
        const float* w1b = &W1s[(lane + 32) * 65];
        #pragma unroll 8
        for (int k = 0; k < CELL; k++) {
            float mv = msS[wid][k];
            acc0 += mv * w1a[k];
            acc1 += mv * w1b[k];
        }
        hidS[wid][lane]      = fmaxf(acc0, 0.f);
        hidS[wid][lane + 32] = fmaxf(acc1, 0.f);
    }
    __syncwarp();

    // ---- MLP2 + tanh (lanes 0..5), then all-shuffle log_softmax
    float pred = 0.f;
    if (lane < Cc) {
        float a = b2[lane];
        const float* w2 = &W2s[lane * 65];
        #pragma unroll 8
        for (int k = 0; k < CELL; k++) a += hidS[wid][k] * w2[k];
        pred = tanhf(a);
    }
    float p0 = __shfl_sync(0xffffffffu, pred, 0);
    float p1 = __shfl_sync(0xffffffffu, pred, 1);
    float p2 = __shfl_sync(0xffffffffu, pred, 2);
    float p3 = __shfl_sync(0xffffffffu, pred, 3);
    float p4 = __shfl_sync(0xffffffffu, pred, 4);
    float p5 = __shfl_sync(0xffffffffu, pred, 5);
    if (lane < Cc) {
        float m = fmaxf(fmaxf(fmaxf(p0, p1), fmaxf(p2, p3)), fmaxf(p4, p5));
        float se = expf(p0 - m) + expf(p1 - m) + expf(p2 - m)
                 + expf(p3 - m) + expf(p4 - m) + expf(p5 - m);
        out[row * Cc + lane] = pred - (m + logf(se));
    }
}

// ---------------------------------------------------------------------------
extern "C" void kernel_launch(void* const* d_in, const int* in_sizes, int n_in,
                              void* d_out, int out_size) {
    const float* x0        = (const float*)d_in[0];
    const float* x1        = (const float*)d_in[1];
    const float* smask     = (const float*)d_in[2];
    const float* umask     = (const float*)d_in[3];
    const float* W_ih0     = (const float*)d_in[4];
    const float* W_hh0     = (const float*)d_in[5];
    const float* b_ih0     = (const float*)d_in[6];
    const float* b_hh0     = (const float*)d_in[7];
    const float* W_ih1     = (const float*)d_in[8];
    const float* W_hh1     = (const float*)d_in[9];
    const float* b_ih1     = (const float*)d_in[10];
    const float* b_hh1     = (const float*)d_in[11];
    const float* phase_tab = (const float*)d_in[12];
    const float* meas_k    = (const float*)d_in[13];
    const float* W1        = (const float*)d_in[14];
    const float* b1        = (const float*)d_in[15];
    const float* W2        = (const float*)d_in[16];
    const float* b2        = (const float*)d_in[17];
    float* out = (float*)d_out;

    dim3 ggrid(5, ROWS / 32, 4);   // (5, 64, 4): 3 mod0 chunks + mod1, uniform K=100
    gemm_xproj<<<ggrid, 256>>>(x0, W_ih0, b_ih0, b_hh0,
                               x1, W_ih1, b_ih1, b_hh1, umask, meas_k);

    reduce_xp0<<<ROWS * G4E / 4 / 256, 256>>>();

    lstm_kernel<<<64, 256>>>(W_hh0, W_hh1);

    epilogue_kernel<<<ROWS / 8, 256>>>(smask, phase_tab, W1, b1, W2, b2, out);
}

// round 10
// speedup vs baseline: 1.7185x; 1.0635x over previous
#include <cuda_runtime.h>
#include <math.h>
#include <stdint.h>

// Problem constants
#define Bb 32
#define Tt 64
#define Ee 64
#define Uu 32
#define D0 300
#define D1 100
#define Ss 9
#define CELL 64
#define Cc 6
#define ROWS (Bb*Tt)      // 2048
#define G4E (4*Ee)        // 256
#define KC 100            // uniform K-chunk

// Device scratch
__device__ float g_xp0a[ROWS * G4E];
__device__ float g_xp0b[ROWS * G4E];
__device__ float g_xp0c[ROWS * G4E];
__device__ float g_xp1 [ROWS * G4E];
__device__ float g_h0[ROWS * Ee];
__device__ float g_h1[ROWS * Ee];
__device__ float2 g_krki[Ee * Uu];   // [e][u] -> (kr, ki), normalized
__device__ float2 g_ph2[Ss * Ee];    // [s][e] -> (cos, sin)

typedef unsigned long long u64;

// ---------------------------------------------------------------------------
__device__ __forceinline__ float tanha(float x) {
    float y;
    asm("tanh.approx.f32 %0, %1;" : "=f"(y) : "f"(x));
    return y;
}
__device__ __forceinline__ float fsig(float x) {
    return fmaf(tanha(0.5f * x), 0.5f, 0.5f);
}
__device__ __forceinline__ u64 ffma2(u64 a, u64 b, u64 c) {
    u64 d;
    asm("fma.rn.f32x2 %0, %1, %2, %3;" : "=l"(d) : "l"(a), "l"(b), "l"(c));
    return d;
}
__device__ __forceinline__ u64 fadd2(u64 a, u64 b) {
    u64 d;
    asm("add.rn.f32x2 %0, %1, %2;" : "=l"(d) : "l"(a), "l"(b));
    return d;
}
__device__ __forceinline__ void unpk2(float& lo, float& hi, u64 v) {
    asm("mov.b64 {%0,%1}, %2;" : "=f"(lo), "=f"(hi) : "l"(v));
}

// ---------------------------------------------------------------------------
// Kernel 1: input-projection GEMM, uniform K=100 chunks + prep slice.
// grid = (5, 32, 4): x in [0,4) -> 64-wide N tiles; x==4,y==0,z==0 -> prep.
// z = 0,1,2 -> mod0 K-chunk z; z = 3 -> mod1.
// BM=64, BN=64, BK=16, 256 thr, 4m x 4n microtile (2 B/MAC smem traffic).
// Double-buffered, 1 barrier/tile.
// ---------------------------------------------------------------------------
#define BKK 16
__global__ void __launch_bounds__(256) gemm_xproj(
    const float* __restrict__ x0, const float* __restrict__ Wih0,
    const float* __restrict__ bih0, const float* __restrict__ bhh0,
    const float* __restrict__ x1, const float* __restrict__ Wih1,
    const float* __restrict__ bih1, const float* __restrict__ bhh1,
    const float* __restrict__ umask, const float* __restrict__ mk,
    const float* __restrict__ phase_tab) {

    if (blockIdx.x == 4) {
        if (blockIdx.y != 0 || blockIdx.z != 0) return;
        // prep: normalize measurement kernel (transposed, packed) + phase LUT
        __shared__ float inv_norm[Uu];
        int tid = threadIdx.x;
        if (tid < Uu) {
            float s = 0.f;
            const float* p = mk + tid * (Ee * 2);
            #pragma unroll 8
            for (int i = 0; i < Ee * 2; i++) s += p[i] * p[i];
            inv_norm[tid] = 1.f / fmaxf(sqrtf(s), 1e-12f);
        }
        __syncthreads();
        for (int idx = tid; idx < Uu * Ee; idx += blockDim.x) {
            int u = idx >> 6;
            int e = idx & 63;
            float inv = inv_norm[u];
            g_krki[e * Uu + u] = make_float2(mk[(u * Ee + e) * 2 + 0] * inv,
                                             mk[(u * Ee + e) * 2 + 1] * inv);
        }
        for (int idx = tid; idx < Ss * Ee; idx += blockDim.x) {
            float p = phase_tab[idx];
            float s, c;
            sincosf(p, &s, &c);
            g_ph2[idx] = make_float2(c, s);
        }
        return;
    }

    int z = blockIdx.z;
    bool mod1 = (z == 3);
    const float* A   = mod1 ? x1 : x0;
    const float* W   = mod1 ? Wih1 : Wih0;
    const float* bih = mod1 ? bih1 : bih0;
    const float* bhh = mod1 ? bhh1 : bhh0;
    float* out = (z == 0) ? g_xp0a : (z == 1) ? g_xp0b : (z == 2) ? g_xp0c : g_xp1;
    const int Ks = mod1 ? D1 : D0;      // row stride
    const int k0 = mod1 ? 0 : z * KC;   // chunk offset
    const bool addb = (z == 0) || mod1;

    __shared__ __align__(16) float As[2][BKK][68];   // [buf][k][m], pad 4
    __shared__ __align__(16) float Ws[2][BKK][68];   // [buf][k][n], pad 4

    int tid = threadIdx.x;
    int lk = tid & 15;          // k within tile
    int lm = tid >> 4;          // 0..15
    int bm = blockIdx.y * 64, bn = blockIdx.x * 64;

    const float* Ab = A + (size_t)(bm + lm) * Ks + k0;
    const float* Wb = W + (size_t)(bn + lm) * Ks + k0;
    const size_t rs = (size_t)16 * Ks;

    const int ntiles = (KC + BKK - 1) / BKK;   // 7

    float av[4], wv[4];
    #pragma unroll
    for (int j = 0; j < 4; j++) {
        av[j] = Ab[j * rs + lk];
        wv[j] = Wb[j * rs + lk];
    }
    #pragma unroll
    for (int j = 0; j < 4; j++) {
        As[0][lk][lm + 16 * j] = av[j];
        Ws[0][lk][lm + 16 * j] = wv[j];
    }
    __syncthreads();

    float acc[4][4];
    #pragma unroll
    for (int i = 0; i < 4; i++)
        #pragma unroll
        for (int j = 0; j < 4; j++) acc[i][j] = 0.f;

    int tx = tid & 15;          // n-quad: cols tx*4..+3
    int ty = tid >> 4;          // m-quad: rows ty*4..+3

    for (int tl = 0; tl < ntiles; tl++) {
        int cur = tl & 1;
        bool has = (tl + 1) < ntiles;
        if (has) {
            int k = (tl + 1) * BKK + lk;
            bool v = k < KC;
            #pragma unroll
            for (int j = 0; j < 4; j++) {
                av[j] = v ? Ab[j * rs + k] : 0.f;
                wv[j] = v ? Wb[j * rs + k] : 0.f;
            }
        }
        #pragma unroll
        for (int kk = 0; kk < BKK; kk++) {
            float4 a4 = *(const float4*)&As[cur][kk][ty * 4];
            float4 w4 = *(const float4*)&Ws[cur][kk][tx * 4];
            float a[4] = {a4.x, a4.y, a4.z, a4.w};
            float w[4] = {w4.x, w4.y, w4.z, w4.w};
            #pragma unroll
            for (int i = 0; i < 4; i++)
                #pragma unroll
                for (int j = 0; j < 4; j++)
                    acc[i][j] += a[i] * w[j];
        }
        if (has) {
            int nb = cur ^ 1;
            #pragma unroll
            for (int j = 0; j < 4; j++) {
                As[nb][lk][lm + 16 * j] = av[j];
                Ws[nb][lk][lm + 16 * j] = wv[j];
            }
        }
        __syncthreads();
    }

    int n = bn + tx * 4;
    float bv0 = 0.f, bv1 = 0.f, bv2 = 0.f, bv3 = 0.f;
    if (addb) {
        bv0 = bih[n + 0] + bhh[n + 0];
        bv1 = bih[n + 1] + bhh[n + 1];
        bv2 = bih[n + 2] + bhh[n + 2];
        bv3 = bih[n + 3] + bhh[n + 3];
    }
    #pragma unroll
    for (int i = 0; i < 4; i++) {
        int m = bm + ty * 4 + i;
        float um = umask[m];
        float4 o;
        o.x = um * acc[i][0] + bv0;
        o.y = um * acc[i][1] + bv1;
        o.z = um * acc[i][2] + bv2;
        o.w = um * acc[i][3] + bv3;
        *(float4*)&out[(size_t)m * G4E + n] = o;
    }
}

// ---------------------------------------------------------------------------
// Kernel 1.5: reduce mod0 chunk partials into g_xp0a (float4, elementwise).
// ---------------------------------------------------------------------------
__global__ void __launch_bounds__(256) reduce_xp0() {
    int i = blockIdx.x * blockDim.x + threadIdx.x;
    float4 a = ((const float4*)g_xp0a)[i];
    float4 b = ((const float4*)g_xp0b)[i];
    float4 c = ((const float4*)g_xp0c)[i];
    a.x += b.x + c.x;
    a.y += b.y + c.y;
    a.z += b.z + c.z;
    a.w += b.w + c.w;
    ((float4*)g_xp0a)[i] = a;
}

// ---------------------------------------------------------------------------
// Kernel 2: LSTM recurrence (measured-best config, unchanged).
// ---------------------------------------------------------------------------
__global__ void __launch_bounds__(256, 1) lstm_kernel(
    const float* __restrict__ Whh0, const float* __restrict__ Whh1) {
    int mod = blockIdx.x >> 5;
    int b = blockIdx.x & 31;
    const float* Whh = mod ? Whh1 : Whh0;
    const float* xp = (mod ? g_xp1 : g_xp0a) + (size_t)b * Tt * G4E;
    float* hout = (mod ? g_h1 : g_h0) + (size_t)b * Tt * Ee;

    int tid = threadIdx.x;
    int w = tid >> 5, l = tid & 31;
    int gt = l & 3;
    int cell = w * 8 + (l >> 2);
    int r = gt * 64 + cell;

    u64 wp[32];
    {
        const float2* src = (const float2*)(Whh + (size_t)r * Ee);
        #pragma unroll
        for (int i = 0; i < 32; i++) {
            union { float2 f; u64 u; } cv;
            cv.f = src[i];
            wp[i] = cv.u;
        }
    }

    __shared__ __align__(16) float hs[2][Ee];
    if (tid < Ee) hs[0][tid] = 0.f;
    float c = 0.f;
    __syncthreads();

    float gpre = xp[r];
    #pragma unroll 1
    for (int t = 0; t < Tt; t++) {
        float gnext = (t + 1 < Tt) ? xp[(t + 1) * G4E + r] : 0.f;

        const ulonglong2* h2 = (const ulonglong2*)hs[t & 1];
        u64 a0 = 0ull, a1 = 0ull, a2 = 0ull, a3 = 0ull;
        #pragma unroll
        for (int i = 0; i < 16; i += 2) {
            ulonglong2 hv = h2[i];
            a0 = ffma2(wp[2 * i + 0], hv.x, a0);
            a1 = ffma2(wp[2 * i + 1], hv.y, a1);
            ulonglong2 hv2 = h2[i + 1];
            a2 = ffma2(wp[2 * i + 2], hv2.x, a2);
            a3 = ffma2(wp[2 * i + 3], hv2.y, a3);
        }
        u64 s = fadd2(fadd2(a0, a1), fadd2(a2, a3));
        float lo, hi;
        unpk2(lo, hi, s);
        float g = gpre + lo + hi;
        gpre = gnext;

        float act = (gt == 2) ? tanha(g) : fsig(g);

        float v1 = __shfl_xor_sync(0xffffffffu, act, 1);
        float v2 = __shfl_xor_sync(0xffffffffu, act, 2);
        float v3 = __shfl_xor_sync(0xffffffffu, act, 3);

        if (gt == 0) {
            c = v1 * c + act * v2;
            float h = tanha(v3 * tanha(c));
            hs[(t + 1) & 1][cell] = h;
            hout[t * Ee + cell] = h;
        }
        __syncthreads();
    }
}

// ---------------------------------------------------------------------------
// Kernel 3: warp-per-row epilogue with shortened dependency chain:
// phase cos/sin LUT staged in smem (argmax-dependent load = LDS not LDG),
// (kr,ki) packed float2, (r0,i0,r1,i1) packed float4.
// ---------------------------------------------------------------------------
__global__ void __launch_bounds__(256) epilogue_kernel(
    const float* __restrict__ smask,
    const float* __restrict__ W1, const float* __restrict__ b1,
    const float* __restrict__ W2, const float* __restrict__ b2,
    float* __restrict__ out) {
    __shared__ __align__(16) float2 krki[Ee * Uu];   // 16KB
    __shared__ __align__(16) float2 ph2s[Ss * Ee];   // 4.6KB
    __shared__ float W1s[CELL * 65];                  // 16.6KB
    __shared__ float W2s[Cc * 65];                    // 1.5KB
    __shared__ __align__(16) float4 riS[8][Ee];       // 8KB (r0,i0,r1,i1)
    __shared__ float msS[8][2 * Uu];
    __shared__ float hidS[8][CELL];

    int tid = threadIdx.x;
    int wid = tid >> 5;
    int lane = tid & 31;

    // stage shared data once per block
    for (int i = tid; i < (Ee * Uu) / 2; i += 256)
        ((float4*)krki)[i] = ((const float4*)g_krki)[i];
    for (int i = tid; i < (Ss * Ee) / 2; i += 256)
        ((float4*)ph2s)[i] = ((const float4*)g_ph2)[i];
    for (int i = tid; i < CELL * CELL; i += 256)
        W1s[(i >> 6) * 65 + (i & 63)] = W1[i];
    for (int i = tid; i < Cc * CELL; i += 256)
        W2s[(i >> 6) * 65 + (i & 63)] = W2[i];
    __syncthreads();

    int row = blockIdx.x * 8 + wid;

    // issue all global loads up front
    const float* h0p = g_h0 + (size_t)row * Ee;
    const float* h1p = g_h1 + (size_t)row * Ee;
    float h0a = h0p[lane], h0b = h0p[lane + 32];
    float h1a = h1p[lane], h1b = h1p[lane + 32];
    float av = (lane < Ss) ? smask[row * Ss + lane] : -1e30f;

    // norms via butterfly
    float v0 = h0a * h0a + h0b * h0b;
    float v1 = h1a * h1a + h1b * h1b;
    int ai = lane;
    #pragma unroll
    for (int off = 16; off; off >>= 1) {
        v0 += __shfl_xor_sync(0xffffffffu, v0, off);
        v1 += __shfl_xor_sync(0xffffffffu, v1, off);
        float ov = __shfl_xor_sync(0xffffffffu, av, off);
        int oi = __shfl_xor_sync(0xffffffffu, ai, off);
        if (ov > av || (ov == av && oi < ai)) { av = ov; ai = oi; }
    }
    float inv0 = 1.f / fmaxf(sqrtf(v0), 1e-12f);
    float inv1 = 1.f / fmaxf(sqrtf(v1), 1e-12f);
    int sidx = ai;

    // phase rotation from smem LUT (29-cyc LDS instead of ~600-cyc LDG)
    float2 pa = ph2s[sidx * Ee + lane];
    float2 pb = ph2s[sidx * Ee + lane + 32];
    float n0a = h0a * inv0, n0b = h0b * inv0;
    float n1a = h1a * inv1, n1b = h1b * inv1;
    riS[wid][lane]      = make_float4(pa.x * n0a, pa.y * n0a, pa.x * n1a, pa.y * n1a);
    riS[wid][lane + 32] = make_float4(pb.x * n0b, pb.y * n0b, pb.x * n1b, pb.y * n1b);
    __syncwarp();

    // measurement: lane u computes m[u] (mod0) and m[32+u] (mod1)
    {
        float pr0 = 0.f, pi0 = 0.f, pr1 = 0.f, pi1 = 0.f;
        #pragma unroll 8
        for (int e = 0; e < Ee; e++) {
            float4 ri = riS[wid][e];             // broadcast LDS.128
            float2 kk = krki[e * Uu + lane];     // LDS.64
            pr0 += kk.x * ri.x - kk.y * ri.y;
            pi0 += kk.y * ri.x + kk.x * ri.y;
            pr1 += kk.x * ri.z - kk.y * ri.w;
            pi1 += kk.y * ri.z + kk.x * ri.w;
        }
        msS[wid][lane]      = pr0 * pr0 + pi0 * pi0;
        msS[wid][lane + 32] = pr1 * pr1 + pi1 * pi1;
    }
    __syncwarp();

    // MLP1: lane handles columns lane and lane+32
    {
        float acc0 = b1[lane], acc1 = b1[lane + 32];
        const float* w1a = &W1s[lane * 65];
        const float* w1b = &W1s[(lane + 32) * 65];
        #pragma unroll 8
        for (int k = 0; k < CELL; k++) {
            float mv = msS[wid][k];
            acc0 += mv * w1a[k];
            acc1 += mv * w1b[k];
        }
        hidS[wid][lane]      = fmaxf(acc0, 0.f);
        hidS[wid][lane + 32] = fmaxf(acc1, 0.f);
    }
    __syncwarp();

    // MLP2 + tanh (lanes 0..5), then all-shuffle log_softmax
    float pred = 0.f;
    if (lane < Cc) {
        float a = b2[lane];
        const float* w2 = &W2s[lane * 65];
        #pragma unroll 8
        for (int k = 0; k < CELL; k++) a += hidS[wid][k] * w2[k];
        pred = tanhf(a);
    }
    float p0 = __shfl_sync(0xffffffffu, pred, 0);
    float p1 = __shfl_sync(0xffffffffu, pred, 1);
    float p2 = __shfl_sync(0xffffffffu, pred, 2);
    float p3 = __shfl_sync(0xffffffffu, pred, 3);
    float p4 = __shfl_sync(0xffffffffu, pred, 4);
    float p5 = __shfl_sync(0xffffffffu, pred, 5);
    if (lane < Cc) {
        float m = fmaxf(fmaxf(fmaxf(p0, p1), fmaxf(p2, p3)), fmaxf(p4, p5));
        float se = expf(p0 - m) + expf(p1 - m) + expf(p2 - m)
                 + expf(p3 - m) + expf(p4 - m) + expf(p5 - m);
        out[row * Cc + lane] = pred - (m + logf(se));
    }
}

// ---------------------------------------------------------------------------
extern "C" void kernel_launch(void* const* d_in, const int* in_sizes, int n_in,
                              void* d_out, int out_size) {
    const float* x0        = (const float*)d_in[0];
    const float* x1        = (const float*)d_in[1];
    const float* smask     = (const float*)d_in[2];
    const float* umask     = (const float*)d_in[3];
    const float* W_ih0     = (const float*)d_in[4];
    const float* W_hh0     = (const float*)d_in[5];
    const float* b_ih0     = (const float*)d_in[6];
    const float* b_hh0     = (const float*)d_in[7];
    const float* W_ih1     = (const float*)d_in[8];
    const float* W_hh1     = (const float*)d_in[9];
    const float* b_ih1     = (const float*)d_in[10];
    const float* b_hh1     = (const float*)d_in[11];
    const float* phase_tab = (const float*)d_in[12];
    const float* meas_k    = (const float*)d_in[13];
    const float* W1        = (const float*)d_in[14];
    const float* b1        = (const float*)d_in[15];
    const float* W2        = (const float*)d_in[16];
    const float* b2        = (const float*)d_in[17];
    float* out = (float*)d_out;

    dim3 ggrid(5, ROWS / 64, 4);   // (5, 32, 4): BM=64 tiles, 3 mod0 chunks + mod1
    gemm_xproj<<<ggrid, 256>>>(x0, W_ih0, b_ih0, b_hh0,
                               x1, W_ih1, b_ih1, b_hh1, umask, meas_k, phase_tab);

    reduce_xp0<<<ROWS * G4E / 4 / 256, 256>>>();

    lstm_kernel<<<64, 256>>>(W_hh0, W_hh1);

    epilogue_kernel<<<ROWS / 8, 256>>>(smask, W1, b1, W2, b2, out);
}

// round 11
// speedup vs baseline: 1.7762x; 1.0336x over previous
#include <cuda_runtime.h>
#include <math.h>
#include <stdint.h>

// Problem constants
#define Bb 32
#define Tt 64
#define Ee 64
#define Uu 32
#define D0 300
#define D1 100
#define Ss 9
#define CELL 64
#define Cc 6
#define ROWS (Bb*Tt)      // 2048
#define G4E (4*Ee)        // 256
#define KC 100            // uniform K-chunk
#define EPW 16            // epilogue rows (warps) per block

// Device scratch
__device__ float g_xp0a[ROWS * G4E];
__device__ float g_xp0b[ROWS * G4E];
__device__ float g_xp0c[ROWS * G4E];
__device__ float g_xp1 [ROWS * G4E];
__device__ float g_h0[ROWS * Ee];
__device__ float g_h1[ROWS * Ee];
__device__ float2 g_krki[Ee * Uu];   // [e][u] -> (kr, ki), normalized
__device__ float2 g_ph2[Ss * Ee];    // [s][e] -> (cos, sin)

typedef unsigned long long u64;

// ---------------------------------------------------------------------------
__device__ __forceinline__ float tanha(float x) {
    float y;
    asm("tanh.approx.f32 %0, %1;" : "=f"(y) : "f"(x));
    return y;
}
__device__ __forceinline__ float fsig(float x) {
    return fmaf(tanha(0.5f * x), 0.5f, 0.5f);
}
__device__ __forceinline__ u64 ffma2(u64 a, u64 b, u64 c) {
    u64 d;
    asm("fma.rn.f32x2 %0, %1, %2, %3;" : "=l"(d) : "l"(a), "l"(b), "l"(c));
    return d;
}
__device__ __forceinline__ u64 fadd2(u64 a, u64 b) {
    u64 d;
    asm("add.rn.f32x2 %0, %1, %2;" : "=l"(d) : "l"(a), "l"(b));
    return d;
}
__device__ __forceinline__ void unpk2(float& lo, float& hi, u64 v) {
    asm("mov.b64 {%0,%1}, %2;" : "=f"(lo), "=f"(hi) : "l"(v));
}

// ---------------------------------------------------------------------------
// Kernel 1: input-projection GEMM, uniform K=100 chunks + prep slice.
// grid = (5, 32, 4). BM=64, BN=64, BK=16, 256 thr, 4m x 4n microtile.
// ---------------------------------------------------------------------------
#define BKK 16
__global__ void __launch_bounds__(256) gemm_xproj(
    const float* __restrict__ x0, const float* __restrict__ Wih0,
    const float* __restrict__ bih0, const float* __restrict__ bhh0,
    const float* __restrict__ x1, const float* __restrict__ Wih1,
    const float* __restrict__ bih1, const float* __restrict__ bhh1,
    const float* __restrict__ umask, const float* __restrict__ mk,
    const float* __restrict__ phase_tab) {

    if (blockIdx.x == 4) {
        if (blockIdx.y != 0 || blockIdx.z != 0) return;
        // prep: normalize measurement kernel (transposed, packed) + phase LUT
        __shared__ float inv_norm[Uu];
        int tid = threadIdx.x;
        if (tid < Uu) {
            float s = 0.f;
            const float* p = mk + tid * (Ee * 2);
            #pragma unroll 8
            for (int i = 0; i < Ee * 2; i++) s += p[i] * p[i];
            inv_norm[tid] = 1.f / fmaxf(sqrtf(s), 1e-12f);
        }
        __syncthreads();
        for (int idx = tid; idx < Uu * Ee; idx += blockDim.x) {
            int u = idx >> 6;
            int e = idx & 63;
            float inv = inv_norm[u];
            g_krki[e * Uu + u] = make_float2(mk[(u * Ee + e) * 2 + 0] * inv,
                                             mk[(u * Ee + e) * 2 + 1] * inv);
        }
        for (int idx = tid; idx < Ss * Ee; idx += blockDim.x) {
            float p = phase_tab[idx];
            float s, c;
            sincosf(p, &s, &c);
            g_ph2[idx] = make_float2(c, s);
        }
        return;
    }

    int z = blockIdx.z;
    bool mod1 = (z == 3);
    const float* A   = mod1 ? x1 : x0;
    const float* W   = mod1 ? Wih1 : Wih0;
    const float* bih = mod1 ? bih1 : bih0;
    const float* bhh = mod1 ? bhh1 : bhh0;
    float* out = (z == 0) ? g_xp0a : (z == 1) ? g_xp0b : (z == 2) ? g_xp0c : g_xp1;
    const int Ks = mod1 ? D1 : D0;
    const int k0 = mod1 ? 0 : z * KC;
    const bool addb = (z == 0) || mod1;

    __shared__ __align__(16) float As[2][BKK][68];
    __shared__ __align__(16) float Ws[2][BKK][68];

    int tid = threadIdx.x;
    int lk = tid & 15;
    int lm = tid >> 4;
    int bm = blockIdx.y * 64, bn = blockIdx.x * 64;

    const float* Ab = A + (size_t)(bm + lm) * Ks + k0;
    const float* Wb = W + (size_t)(bn + lm) * Ks + k0;
    const size_t rs = (size_t)16 * Ks;

    const int ntiles = (KC + BKK - 1) / BKK;   // 7

    float av[4], wv[4];
    #pragma unroll
    for (int j = 0; j < 4; j++) {
        av[j] = Ab[j * rs + lk];
        wv[j] = Wb[j * rs + lk];
    }
    #pragma unroll
    for (int j = 0; j < 4; j++) {
        As[0][lk][lm + 16 * j] = av[j];
        Ws[0][lk][lm + 16 * j] = wv[j];
    }
    __syncthreads();

    float acc[4][4];
    #pragma unroll
    for (int i = 0; i < 4; i++)
        #pragma unroll
        for (int j = 0; j < 4; j++) acc[i][j] = 0.f;

    int tx = tid & 15;
    int ty = tid >> 4;

    for (int tl = 0; tl < ntiles; tl++) {
        int cur = tl & 1;
        bool has = (tl + 1) < ntiles;
        if (has) {
            int k = (tl + 1) * BKK + lk;
            bool v = k < KC;
            #pragma unroll
            for (int j = 0; j < 4; j++) {
                av[j] = v ? Ab[j * rs + k] : 0.f;
                wv[j] = v ? Wb[j * rs + k] : 0.f;
            }
        }
        #pragma unroll
        for (int kk = 0; kk < BKK; kk++) {
            float4 a4 = *(const float4*)&As[cur][kk][ty * 4];
            float4 w4 = *(const float4*)&Ws[cur][kk][tx * 4];
            float a[4] = {a4.x, a4.y, a4.z, a4.w};
            float w[4] = {w4.x, w4.y, w4.z, w4.w};
            #pragma unroll
            for (int i = 0; i < 4; i++)
                #pragma unroll
                for (int j = 0; j < 4; j++)
                    acc[i][j] += a[i] * w[j];
        }
        if (has) {
            int nb = cur ^ 1;
            #pragma unroll
            for (int j = 0; j < 4; j++) {
                As[nb][lk][lm + 16 * j] = av[j];
                Ws[nb][lk][lm + 16 * j] = wv[j];
            }
        }
        __syncthreads();
    }

    int n = bn + tx * 4;
    float bv0 = 0.f, bv1 = 0.f, bv2 = 0.f, bv3 = 0.f;
    if (addb) {
        bv0 = bih[n + 0] + bhh[n + 0];
        bv1 = bih[n + 1] + bhh[n + 1];
        bv2 = bih[n + 2] + bhh[n + 2];
        bv3 = bih[n + 3] + bhh[n + 3];
    }
    #pragma unroll
    for (int i = 0; i < 4; i++) {
        int m = bm + ty * 4 + i;
        float um = umask[m];
        float4 o;
        o.x = um * acc[i][0] + bv0;
        o.y = um * acc[i][1] + bv1;
        o.z = um * acc[i][2] + bv2;
        o.w = um * acc[i][3] + bv3;
        *(float4*)&out[(size_t)m * G4E + n] = o;
    }
}

// ---------------------------------------------------------------------------
// Kernel 1.5: reduce mod0 chunk partials into g_xp0a.
// ---------------------------------------------------------------------------
__global__ void __launch_bounds__(256) reduce_xp0() {
    int i = blockIdx.x * blockDim.x + threadIdx.x;
    float4 a = ((const float4*)g_xp0a)[i];
    float4 b = ((const float4*)g_xp0b)[i];
    float4 c = ((const float4*)g_xp0c)[i];
    a.x += b.x + c.x;
    a.y += b.y + c.y;
    a.z += b.z + c.z;
    a.w += b.w + c.w;
    ((float4*)g_xp0a)[i] = a;
}

// ---------------------------------------------------------------------------
// Kernel 2: LSTM recurrence (measured-best config, unchanged).
// ---------------------------------------------------------------------------
__global__ void __launch_bounds__(256, 1) lstm_kernel(
    const float* __restrict__ Whh0, const float* __restrict__ Whh1) {
    int mod = blockIdx.x >> 5;
    int b = blockIdx.x & 31;
    const float* Whh = mod ? Whh1 : Whh0;
    const float* xp = (mod ? g_xp1 : g_xp0a) + (size_t)b * Tt * G4E;
    float* hout = (mod ? g_h1 : g_h0) + (size_t)b * Tt * Ee;

    int tid = threadIdx.x;
    int w = tid >> 5, l = tid & 31;
    int gt = l & 3;
    int cell = w * 8 + (l >> 2);
    int r = gt * 64 + cell;

    u64 wp[32];
    {
        const float2* src = (const float2*)(Whh + (size_t)r * Ee);
        #pragma unroll
        for (int i = 0; i < 32; i++) {
            union { float2 f; u64 u; } cv;
            cv.f = src[i];
            wp[i] = cv.u;
        }
    }

    __shared__ __align__(16) float hs[2][Ee];
    if (tid < Ee) hs[0][tid] = 0.f;
    float c = 0.f;
    __syncthreads();

    float gpre = xp[r];
    #pragma unroll 1
    for (int t = 0; t < Tt; t++) {
        float gnext = (t + 1 < Tt) ? xp[(t + 1) * G4E + r] : 0.f;

        const ulonglong2* h2 = (const ulonglong2*)hs[t & 1];
        u64 a0 = 0ull, a1 = 0ull, a2 = 0ull, a3 = 0ull;
        #pragma unroll
        for (int i = 0; i < 16; i += 2) {
            ulonglong2 hv = h2[i];
            a0 = ffma2(wp[2 * i + 0], hv.x, a0);
            a1 = ffma2(wp[2 * i + 1], hv.y, a1);
            ulonglong2 hv2 = h2[i + 1];
            a2 = ffma2(wp[2 * i + 2], hv2.x, a2);
            a3 = ffma2(wp[2 * i + 3], hv2.y, a3);
        }
        u64 s = fadd2(fadd2(a0, a1), fadd2(a2, a3));
        float lo, hi;
        unpk2(lo, hi, s);
        float g = gpre + lo + hi;
        gpre = gnext;

        float act = (gt == 2) ? tanha(g) : fsig(g);

        float v1 = __shfl_xor_sync(0xffffffffu, act, 1);
        float v2 = __shfl_xor_sync(0xffffffffu, act, 2);
        float v3 = __shfl_xor_sync(0xffffffffu, act, 3);

        if (gt == 0) {
            c = v1 * c + act * v2;
            float h = tanha(v3 * tanha(c));
            hs[(t + 1) & 1][cell] = h;
            hout[t * Ee + cell] = h;
        }
        __syncthreads();
    }
}

// ---------------------------------------------------------------------------
// Kernel 3: warp-per-row epilogue, 16 rows/block (512 thr), h prefetched
// before the staging barrier, MUFU tail.
// ---------------------------------------------------------------------------
__global__ void __launch_bounds__(512) epilogue_kernel(
    const float* __restrict__ smask,
    const float* __restrict__ W1, const float* __restrict__ b1,
    const float* __restrict__ W2, const float* __restrict__ b2,
    float* __restrict__ out) {
    __shared__ __align__(16) float2 krki[Ee * Uu];     // 16KB
    __shared__ __align__(16) float2 ph2s[Ss * Ee];     // 4.6KB
    __shared__ float W1s[CELL * 65];                    // 16.6KB
    __shared__ float W2s[Cc * 65];                      // 1.5KB
    __shared__ __align__(16) float4 riS[EPW][Ee];       // 16KB
    __shared__ float msS[EPW][2 * Uu];                  // 4KB
    __shared__ float hidS[EPW][CELL];                   // 4KB

    int tid = threadIdx.x;
    int wid = tid >> 5;
    int lane = tid & 31;
    int row = blockIdx.x * EPW + wid;

    // ---- prefetch global row data FIRST (latency overlaps staging below)
    const float* h0p = g_h0 + (size_t)row * Ee;
    const float* h1p = g_h1 + (size_t)row * Ee;
    float h0a = h0p[lane], h0b = h0p[lane + 32];
    float h1a = h1p[lane], h1b = h1p[lane + 32];
    float av = (lane < Ss) ? smask[row * Ss + lane] : -1e30f;

    // ---- stage shared data (512-thread strides)
    for (int i = tid; i < (Ee * Uu) / 2; i += 512)
        ((float4*)krki)[i] = ((const float4*)g_krki)[i];
    for (int i = tid; i < (Ss * Ee) / 2; i += 512)
        ((float4*)ph2s)[i] = ((const float4*)g_ph2)[i];
    for (int i = tid; i < CELL * CELL; i += 512)
        W1s[(i >> 6) * 65 + (i & 63)] = W1[i];
    for (int i = tid; i < Cc * CELL; i += 512)
        W2s[(i >> 6) * 65 + (i & 63)] = W2[i];
    __syncthreads();

    // ---- norms + argmax via one fused butterfly
    float v0 = h0a * h0a + h0b * h0b;
    float v1 = h1a * h1a + h1b * h1b;
    int ai = lane;
    #pragma unroll
    for (int off = 16; off; off >>= 1) {
        v0 += __shfl_xor_sync(0xffffffffu, v0, off);
        v1 += __shfl_xor_sync(0xffffffffu, v1, off);
        float ov = __shfl_xor_sync(0xffffffffu, av, off);
        int oi = __shfl_xor_sync(0xffffffffu, ai, off);
        if (ov > av || (ov == av && oi < ai)) { av = ov; ai = oi; }
    }
    float inv0 = rsqrtf(fmaxf(v0, 1e-24f));
    float inv1 = rsqrtf(fmaxf(v1, 1e-24f));
    int sidx = ai;

    // ---- phase rotation from smem LUT
    float2 pa = ph2s[sidx * Ee + lane];
    float2 pb = ph2s[sidx * Ee + lane + 32];
    float n0a = h0a * inv0, n0b = h0b * inv0;
    float n1a = h1a * inv1, n1b = h1b * inv1;
    riS[wid][lane]      = make_float4(pa.x * n0a, pa.y * n0a, pa.x * n1a, pa.y * n1a);
    riS[wid][lane + 32] = make_float4(pb.x * n0b, pb.y * n0b, pb.x * n1b, pb.y * n1b);
    __syncwarp();

    // ---- measurement: lane u computes m[u] (mod0) and m[32+u] (mod1)
    {
        float pr0 = 0.f, pi0 = 0.f, pr1 = 0.f, pi1 = 0.f;
        #pragma unroll 8
        for (int e = 0; e < Ee; e++) {
            float4 ri = riS[wid][e];
            float2 kk = krki[e * Uu + lane];
            pr0 += kk.x * ri.x - kk.y * ri.y;
            pi0 += kk.y * ri.x + kk.x * ri.y;
            pr1 += kk.x * ri.z - kk.y * ri.w;
            pi1 += kk.y * ri.z + kk.x * ri.w;
        }
        msS[wid][lane]      = pr0 * pr0 + pi0 * pi0;
        msS[wid][lane + 32] = pr1 * pr1 + pi1 * pi1;
    }
    __syncwarp();

    // ---- MLP1
    {
        float acc0 = b1[lane], acc1 = b1[lane + 32];
        const float* w1a = &W1s[lane * 65];
        const float* w1b = &W1s[(lane + 32) * 65];
        #pragma unroll 8
        for (int k = 0; k < CELL; k++) {
            float mv = msS[wid][k];
            acc0 += mv * w1a[k];
            acc1 += mv * w1b[k];
        }
        hidS[wid][lane]      = fmaxf(acc0, 0.f);
        hidS[wid][lane + 32] = fmaxf(acc1, 0.f);
    }
    __syncwarp();

    // ---- MLP2 + tanh (lanes 0..5) + all-shuffle log_softmax (fast math)
    float pred = 0.f;
    if (lane < Cc) {
        float a = b2[lane];
        const float* w2 = &W2s[lane * 65];
        #pragma unroll 8
        for (int k = 0; k < CELL; k++) a += hidS[wid][k] * w2[k];
        pred = tanha(a);
    }
    float p0 = __shfl_sync(0xffffffffu, pred, 0);
    float p1 = __shfl_sync(0xffffffffu, pred, 1);
    float p2 = __shfl_sync(0xffffffffu, pred, 2);
    float p3 = __shfl_sync(0xffffffffu, pred, 3);
    float p4 = __shfl_sync(0xffffffffu, pred, 4);
    float p5 = __shfl_sync(0xffffffffu, pred, 5);
    if (lane < Cc) {
        float m = fmaxf(fmaxf(fmaxf(p0, p1), fmaxf(p2, p3)), fmaxf(p4, p5));
        float se = __expf(p0 - m) + __expf(p1 - m) + __expf(p2 - m)
                 + __expf(p3 - m) + __expf(p4 - m) + __expf(p5 - m);
        out[row * Cc + lane] = pred - (m + __logf(se));
    }
}

// ---------------------------------------------------------------------------
extern "C" void kernel_launch(void* const* d_in, const int* in_sizes, int n_in,
                              void* d_out, int out_size) {
    const float* x0        = (const float*)d_in[0];
    const float* x1        = (const float*)d_in[1];
    const float* smask     = (const float*)d_in[2];
    const float* umask     = (const float*)d_in[3];
    const float* W_ih0     = (const float*)d_in[4];
    const float* W_hh0     = (const float*)d_in[5];
    const float* b_ih0     = (const float*)d_in[6];
    const float* b_hh0     = (const float*)d_in[7];
    const float* W_ih1     = (const float*)d_in[8];
    const float* W_hh1     = (const float*)d_in[9];
    const float* b_ih1     = (const float*)d_in[10];
    const float* b_hh1     = (const float*)d_in[11];
    const float* phase_tab = (const float*)d_in[12];
    const float* meas_k    = (const float*)d_in[13];
    const float* W1        = (const float*)d_in[14];
    const float* b1        = (const float*)d_in[15];
    const float* W2        = (const float*)d_in[16];
    const float* b2        = (const float*)d_in[17];
    float* out = (float*)d_out;

    dim3 ggrid(5, ROWS / 64, 4);
    gemm_xproj<<<ggrid, 256>>>(x0, W_ih0, b_ih0, b_hh0,
                               x1, W_ih1, b_ih1, b_hh1, umask, meas_k, phase_tab);

    reduce_xp0<<<ROWS * G4E / 4 / 256, 256>>>();

    lstm_kernel<<<64, 256>>>(W_hh0, W_hh1);

    epilogue_kernel<<<ROWS / EPW, 512>>>(smask, W1, b1, W2, b2, out);
}